// round 1
// baseline (speedup 1.0000x reference)
#include <cuda_runtime.h>
#include <cuda_bf16.h>

// Problem constants
#define HIDDEN 1024
#define SEQ    2048
#define BATCH  2
#define HEADS  16
#define HD     64
#define MTOT   (BATCH*SEQ)   // 4096

// Scratch (device globals: no allocation allowed)
__device__ float g_q [BATCH*SEQ*HIDDEN];
__device__ float g_k [BATCH*SEQ*HIDDEN];
__device__ float g_v [BATCH*SEQ*HIDDEN];
__device__ float g_ao[BATCH*SEQ*HIDDEN];

// ---------------------------------------------------------------------------
// FP32 GEMM body: C[M=4096? x N=1024] = A[M,1024] @ B[1024,1024] + bias
// Block tile 128x128, K-tile 16, 256 threads (16x16), 8x8 micro-tile.
// A staged transposed in SMEM (outer-product friendly), B natural.
// ---------------------------------------------------------------------------
__device__ __forceinline__ void gemm_body(
    const float* __restrict__ A, const float* __restrict__ B,
    const float* __restrict__ bias, float* __restrict__ C,
    int m0, int n0)
{
    __shared__ float As[16][132];   // [k][m], padded
    __shared__ float Bs[16][132];   // [k][n], padded

    const int tid = threadIdx.x;
    const int tx = tid & 15;
    const int ty = tid >> 4;

    float acc[8][8];
#pragma unroll
    for (int i = 0; i < 8; i++)
#pragma unroll
        for (int j = 0; j < 8; j++) acc[i][j] = 0.0f;

    for (int k0 = 0; k0 < HIDDEN; k0 += 16) {
        // Load A tile 128x16 (transposed into SMEM). 512 float4, 2 per thread.
#pragma unroll
        for (int l = 0; l < 2; l++) {
            int fi = tid + 256 * l;
            int m  = fi >> 2;
            int k4 = (fi & 3) << 2;
            float4 v = *(const float4*)&A[(size_t)(m0 + m) * HIDDEN + k0 + k4];
            As[k4 + 0][m] = v.x;
            As[k4 + 1][m] = v.y;
            As[k4 + 2][m] = v.z;
            As[k4 + 3][m] = v.w;
        }
        // Load B tile 16x128. 512 float4, 2 per thread.
#pragma unroll
        for (int l = 0; l < 2; l++) {
            int fi = tid + 256 * l;
            int kk = fi >> 5;
            int c4 = (fi & 31) << 2;
            *(float4*)&Bs[kk][c4] =
                *(const float4*)&B[(size_t)(k0 + kk) * HIDDEN + n0 + c4];
        }
        __syncthreads();

#pragma unroll
        for (int kk = 0; kk < 16; kk++) {
            float4 a0 = *(const float4*)&As[kk][ty * 4];
            float4 a1 = *(const float4*)&As[kk][64 + ty * 4];
            float4 b0 = *(const float4*)&Bs[kk][tx * 4];
            float4 b1 = *(const float4*)&Bs[kk][64 + tx * 4];
            float a[8] = {a0.x, a0.y, a0.z, a0.w, a1.x, a1.y, a1.z, a1.w};
            float b[8] = {b0.x, b0.y, b0.z, b0.w, b1.x, b1.y, b1.z, b1.w};
#pragma unroll
            for (int i = 0; i < 8; i++)
#pragma unroll
                for (int j = 0; j < 8; j++)
                    acc[i][j] = fmaf(a[i], b[j], acc[i][j]);
        }
        __syncthreads();
    }

    // Epilogue: bias + store (float4)
    float4 bb0 = *(const float4*)&bias[n0 + tx * 4];
    float4 bb1 = *(const float4*)&bias[n0 + 64 + tx * 4];
    float bc[8] = {bb0.x, bb0.y, bb0.z, bb0.w, bb1.x, bb1.y, bb1.z, bb1.w};

#pragma unroll
    for (int i = 0; i < 8; i++) {
        int r = m0 + ((i < 4) ? (ty * 4 + i) : (64 + ty * 4 + i - 4));
        float4 o0 = make_float4(acc[i][0] + bc[0], acc[i][1] + bc[1],
                                acc[i][2] + bc[2], acc[i][3] + bc[3]);
        float4 o1 = make_float4(acc[i][4] + bc[4], acc[i][5] + bc[5],
                                acc[i][6] + bc[6], acc[i][7] + bc[7]);
        *(float4*)&C[(size_t)r * HIDDEN + n0 + tx * 4]      = o0;
        *(float4*)&C[(size_t)r * HIDDEN + n0 + 64 + tx * 4] = o1;
    }
}

// QKV: one launch, blockIdx.z selects which projection.
__global__ __launch_bounds__(256) void qkv_kernel(
    const float* __restrict__ x,
    const float* __restrict__ Wq, const float* __restrict__ bq,
    const float* __restrict__ Wk, const float* __restrict__ bk,
    const float* __restrict__ Wv, const float* __restrict__ bv)
{
    const float* B;
    const float* bias;
    float* C;
    if (blockIdx.z == 0)      { B = Wq; bias = bq; C = g_q; }
    else if (blockIdx.z == 1) { B = Wk; bias = bk; C = g_k; }
    else                      { B = Wv; bias = bv; C = g_v; }
    gemm_body(x, B, bias, C, blockIdx.y * 128, blockIdx.x * 128);
}

__global__ __launch_bounds__(256) void oproj_kernel(
    const float* __restrict__ Wo, const float* __restrict__ bo,
    float* __restrict__ out)
{
    gemm_body(g_ao, Wo, bo, out, blockIdx.y * 128, blockIdx.x * 128);
}

// ---------------------------------------------------------------------------
// Flash attention, fp32. One block per (q-tile of 64, head, batch).
// BM=64 queries, BN=64 keys per tile, hd=64.
// 256 threads as 16x16; each thread owns rows {ty+16i} x cols {tx+16j} (4x4).
// Dot products vectorized float4 along the reduction dim.
// SMEM: Qs[64][68], Ks[64][68], Vt[64][68] (transposed: [d][key]), Ps[64][68]
// ---------------------------------------------------------------------------
#define ATT_SMEM (4 * 64 * 68 * 4)

__global__ __launch_bounds__(256) void attn_kernel(float* __restrict__ Oout)
{
    extern __shared__ float sm[];
    float (*Qs)[68] = (float(*)[68])(sm);
    float (*Ks)[68] = (float(*)[68])(sm + 64 * 68);
    float (*Vt)[68] = (float(*)[68])(sm + 2 * 64 * 68);
    float (*Ps)[68] = (float(*)[68])(sm + 3 * 64 * 68);

    const int tid = threadIdx.x;
    const int tx = tid & 15;
    const int ty = tid >> 4;
    const int q0 = blockIdx.x * 64;
    const int h  = blockIdx.y;
    const int b  = blockIdx.z;
    const size_t base = (size_t)b * SEQ * HIDDEN + (size_t)h * HD;

    // Load Q tile [64 rows][64 dims]
#pragma unroll
    for (int l = 0; l < 4; l++) {
        int fi = tid + 256 * l;         // 0..1023
        int r  = fi >> 4;               // 0..63
        int d4 = (fi & 15) << 2;        // 0..60
        *(float4*)&Qs[r][d4] =
            *(const float4*)&g_q[base + (size_t)(q0 + r) * HIDDEN + d4];
    }

    float o[4][4];
    float mrow[4], lrow[4];
#pragma unroll
    for (int i = 0; i < 4; i++) {
        mrow[i] = -1e30f;
        lrow[i] = 0.0f;
#pragma unroll
        for (int j = 0; j < 4; j++) o[i][j] = 0.0f;
    }

    for (int kt = 0; kt < SEQ; kt += 64) {
        __syncthreads();   // previous tile fully consumed (also covers Q load)

        // Load K tile [64 keys][64 dims]
#pragma unroll
        for (int l = 0; l < 4; l++) {
            int fi = tid + 256 * l;
            int r  = fi >> 4;
            int d4 = (fi & 15) << 2;
            *(float4*)&Ks[r][d4] =
                *(const float4*)&g_k[base + (size_t)(kt + r) * HIDDEN + d4];
        }
        // Load V transposed: Vt[d][key]
#pragma unroll
        for (int p = 0; p < 16; p++) {
            int fi = tid + 256 * p;     // 0..4095
            int c  = fi >> 6;           // key 0..63
            int d  = fi & 63;
            Vt[d][c] = g_v[base + (size_t)(kt + c) * HIDDEN + d];
        }
        __syncthreads();

        // S = Q K^T (scaled)
        float s[4][4];
#pragma unroll
        for (int i = 0; i < 4; i++)
#pragma unroll
            for (int j = 0; j < 4; j++) s[i][j] = 0.0f;

#pragma unroll
        for (int d = 0; d < 64; d += 4) {
            float4 av[4], bv[4];
#pragma unroll
            for (int i = 0; i < 4; i++) av[i] = *(const float4*)&Qs[ty + 16 * i][d];
#pragma unroll
            for (int j = 0; j < 4; j++) bv[j] = *(const float4*)&Ks[tx + 16 * j][d];
#pragma unroll
            for (int i = 0; i < 4; i++)
#pragma unroll
                for (int j = 0; j < 4; j++) {
                    s[i][j] = fmaf(av[i].x, bv[j].x, s[i][j]);
                    s[i][j] = fmaf(av[i].y, bv[j].y, s[i][j]);
                    s[i][j] = fmaf(av[i].z, bv[j].z, s[i][j]);
                    s[i][j] = fmaf(av[i].w, bv[j].w, s[i][j]);
                }
        }

        // Online softmax (row reductions across the 16 tx lanes of each half-warp)
#pragma unroll
        for (int i = 0; i < 4; i++) {
            float tmax = -1e30f;
#pragma unroll
            for (int j = 0; j < 4; j++) {
                s[i][j] *= 0.125f;      // 1/sqrt(64)
                tmax = fmaxf(tmax, s[i][j]);
            }
#pragma unroll
            for (int off = 8; off >= 1; off >>= 1)
                tmax = fmaxf(tmax, __shfl_xor_sync(0xffffffffu, tmax, off));

            float mn = fmaxf(mrow[i], tmax);
            float corr = __expf(mrow[i] - mn);
            mrow[i] = mn;
            lrow[i] *= corr;
#pragma unroll
            for (int j = 0; j < 4; j++) o[i][j] *= corr;

            float ps = 0.0f;
#pragma unroll
            for (int j = 0; j < 4; j++) {
                float p = __expf(s[i][j] - mn);
                ps += p;
                Ps[ty + 16 * i][tx + 16 * j] = p;
            }
#pragma unroll
            for (int off = 8; off >= 1; off >>= 1)
                ps += __shfl_xor_sync(0xffffffffu, ps, off);
            lrow[i] += ps;
        }
        __syncthreads();   // Ps visible to all

        // O += P @ V   (reduction over the 64 keys, float4 along key dim)
#pragma unroll
        for (int c = 0; c < 64; c += 4) {
            float4 av[4], bv[4];
#pragma unroll
            for (int i = 0; i < 4; i++) av[i] = *(const float4*)&Ps[ty + 16 * i][c];
#pragma unroll
            for (int j = 0; j < 4; j++) bv[j] = *(const float4*)&Vt[tx + 16 * j][c];
#pragma unroll
            for (int i = 0; i < 4; i++)
#pragma unroll
                for (int j = 0; j < 4; j++) {
                    o[i][j] = fmaf(av[i].x, bv[j].x, o[i][j]);
                    o[i][j] = fmaf(av[i].y, bv[j].y, o[i][j]);
                    o[i][j] = fmaf(av[i].z, bv[j].z, o[i][j]);
                    o[i][j] = fmaf(av[i].w, bv[j].w, o[i][j]);
                }
        }
    }

    // Normalize and write [b, q, h, d] (coalesced across tx)
#pragma unroll
    for (int i = 0; i < 4; i++) {
        float inv = 1.0f / lrow[i];
#pragma unroll
        for (int j = 0; j < 4; j++) {
            g_ao[base + (size_t)(q0 + ty + 16 * i) * HIDDEN + tx + 16 * j] =
                o[i][j] * inv;
        }
    }
    (void)Oout;
}

// ---------------------------------------------------------------------------
extern "C" void kernel_launch(void* const* d_in, const int* in_sizes, int n_in,
                              void* d_out, int out_size)
{
    const float* x  = (const float*)d_in[0];
    const float* Wq = (const float*)d_in[1];
    const float* bq = (const float*)d_in[2];
    const float* Wk = (const float*)d_in[3];
    const float* bk = (const float*)d_in[4];
    const float* Wv = (const float*)d_in[5];
    const float* bv = (const float*)d_in[6];
    const float* Wo = (const float*)d_in[7];
    const float* bo = (const float*)d_in[8];
    float* out = (float*)d_out;

    // QKV projections: grid (Ntiles=8, Mtiles=32, 3)
    dim3 qkvGrid(HIDDEN / 128, MTOT / 128, 3);
    qkv_kernel<<<qkvGrid, 256>>>(x, Wq, bq, Wk, bk, Wv, bv);

    // Attention: (q-tiles=32, heads=16, batch=2)
    cudaFuncSetAttribute(attn_kernel,
                         cudaFuncAttributeMaxDynamicSharedMemorySize, ATT_SMEM);
    attn_kernel<<<dim3(SEQ / 64, HEADS, BATCH), 256, ATT_SMEM>>>(nullptr);

    // Output projection
    dim3 oGrid(HIDDEN / 128, MTOT / 128, 1);
    oproj_kernel<<<oGrid, 256>>>(Wo, bo, out);
}

// round 3
// speedup vs baseline: 1.2912x; 1.2912x over previous
#include <cuda_runtime.h>
#include <cuda_bf16.h>
#include <cstdint>

#define HIDDEN 1024
#define SEQ    2048
#define BATCH  2
#define HEADS  16
#define HD     64
#define MTOT   (BATCH*SEQ)   // 4096

typedef __nv_bfloat16 bf16;

// ---------------- scratch (device globals; no allocations allowed) ----------
__device__ float g_q [MTOT*HIDDEN];
__device__ float g_k [MTOT*HIDDEN];
__device__ float g_v [MTOT*HIDDEN];
__device__ float g_ao[MTOT*HIDDEN];
__device__ bf16  g_xh [MTOT*HIDDEN];
__device__ bf16  g_xl [MTOT*HIDDEN];
__device__ bf16  g_aoh[MTOT*HIDDEN];
__device__ bf16  g_aol[MTOT*HIDDEN];
__device__ bf16  g_wth[4*HIDDEN*HIDDEN];   // W^T hi, [n][k]
__device__ bf16  g_wtl[4*HIDDEN*HIDDEN];   // W^T lo

// ---------------- helpers ----------------------------------------------------
__device__ __forceinline__ uint32_t smem_u32(const void* p) {
    uint32_t a;
    asm("{ .reg .u64 t; cvta.to.shared.u64 t, %1; cvt.u32.u64 %0, t; }"
        : "=r"(a) : "l"(p));
    return a;
}
__device__ __forceinline__ void cpasync16(uint32_t dst, const void* src) {
    asm volatile("cp.async.cg.shared.global [%0], [%1], 16;"
                 :: "r"(dst), "l"(src));
}
#define CP_COMMIT() asm volatile("cp.async.commit_group;" ::: "memory")
#define CP_WAIT1()  asm volatile("cp.async.wait_group 1;"  ::: "memory")
#define CP_WAIT0()  asm volatile("cp.async.wait_group 0;"  ::: "memory")

__device__ __forceinline__ void mma_bf16(float* c, const uint32_t* a,
                                         const uint32_t* b) {
    asm volatile(
        "mma.sync.aligned.m16n8k16.row.col.f32.bf16.bf16.f32 "
        "{%0,%1,%2,%3}, {%4,%5,%6,%7}, {%8,%9}, {%0,%1,%2,%3};"
        : "+f"(c[0]), "+f"(c[1]), "+f"(c[2]), "+f"(c[3])
        : "r"(a[0]), "r"(a[1]), "r"(a[2]), "r"(a[3]), "r"(b[0]), "r"(b[1]));
}

// ---------------- prep: split fp32 -> bf16 hi/lo -----------------------------
__device__ __forceinline__ void split4(float4 v, ushort4& hv, ushort4& lv) {
    bf16 h0 = __float2bfloat16(v.x), h1 = __float2bfloat16(v.y);
    bf16 h2 = __float2bfloat16(v.z), h3 = __float2bfloat16(v.w);
    hv.x = __bfloat16_as_ushort(h0); hv.y = __bfloat16_as_ushort(h1);
    hv.z = __bfloat16_as_ushort(h2); hv.w = __bfloat16_as_ushort(h3);
    lv.x = __bfloat16_as_ushort(__float2bfloat16(v.x - __bfloat162float(h0)));
    lv.y = __bfloat16_as_ushort(__float2bfloat16(v.y - __bfloat162float(h1)));
    lv.z = __bfloat16_as_ushort(__float2bfloat16(v.z - __bfloat162float(h2)));
    lv.w = __bfloat16_as_ushort(__float2bfloat16(v.w - __bfloat162float(h3)));
}
__global__ __launch_bounds__(256) void split_x_kernel(const float* __restrict__ src) {
    int i = (blockIdx.x * 256 + threadIdx.x) * 4;
    ushort4 hv, lv;
    split4(*(const float4*)&src[i], hv, lv);
    *(ushort4*)&g_xh[i] = hv;
    *(ushort4*)&g_xl[i] = lv;
}
__global__ __launch_bounds__(256) void split_ao_kernel() {
    int i = (blockIdx.x * 256 + threadIdx.x) * 4;
    ushort4 hv, lv;
    split4(*(const float4*)&g_ao[i], hv, lv);
    *(ushort4*)&g_aoh[i] = hv;
    *(ushort4*)&g_aol[i] = lv;
}

// ---------------- transpose + split weights: W[K][N] -> Wt[N][K] hi/lo -------
__global__ __launch_bounds__(256) void wtrans_kernel(
    const float* __restrict__ W0, const float* __restrict__ W1,
    const float* __restrict__ W2, const float* __restrict__ W3)
{
    __shared__ float t[32][33];
    const float* W = (blockIdx.z == 0) ? W0 : (blockIdx.z == 1) ? W1
                   : (blockIdx.z == 2) ? W2 : W3;
    bf16* oh = g_wth + (size_t)blockIdx.z * HIDDEN * HIDDEN;
    bf16* ol = g_wtl + (size_t)blockIdx.z * HIDDEN * HIDDEN;
    int n0 = blockIdx.x * 32, k0 = blockIdx.y * 32;
    int tx = threadIdx.x, ty = threadIdx.y;
#pragma unroll
    for (int i = 0; i < 4; i++)
        t[ty + 8 * i][tx] = W[(size_t)(k0 + ty + 8 * i) * HIDDEN + n0 + tx];
    __syncthreads();
#pragma unroll
    for (int i = 0; i < 4; i++) {
        float v = t[tx][ty + 8 * i];
        bf16 h = __float2bfloat16(v);
        bf16 l = __float2bfloat16(v - __bfloat162float(h));
        size_t o = (size_t)(n0 + ty + 8 * i) * HIDDEN + k0 + tx;
        oh[o] = h;
        ol[o] = l;
    }
}

// ---------------- bf16x3 GEMM via mma.sync ------------------------------------
// CTA 128x128, K-chunk 32, 256 threads (8 warps, 2x4), warp tile 64x32.
// SMEM row stride 40 bf16 (80B, 16B-aligned, conflict-free banks).
#define KCH    32
#define NCHK   (HIDDEN / KCH)   // 32
#define RS_BF  40
#define RS_U32 20
#define ARR_B  (128 * RS_BF * 2)     // 10240 bytes per array
#define STG_B  (4 * ARR_B)           // 40960 bytes per stage
#define GSMEM  (2 * STG_B)           // 81920 bytes

__device__ __forceinline__ void g_load_stage(
    uint32_t sbase, const bf16* __restrict__ Ah, const bf16* __restrict__ Al,
    const bf16* __restrict__ Bh, const bf16* __restrict__ Bl, int ko, int tid)
{
#pragma unroll
    for (int l = 0; l < 2; l++) {
        int fi  = tid + 256 * l;
        int row = fi >> 2;
        int w   = fi & 3;
        uint32_t so = sbase + (uint32_t)(row * 80 + w * 16);
        size_t   go = (size_t)row * HIDDEN + ko + w * 8;
        cpasync16(so + 0 * ARR_B, Ah + go);
        cpasync16(so + 1 * ARR_B, Al + go);
        cpasync16(so + 2 * ARR_B, Bh + go);
        cpasync16(so + 3 * ARR_B, Bl + go);
    }
}

__device__ __forceinline__ void g_compute(
    const uint32_t* __restrict__ s, int m_w, int n_w, int lr, int lc,
    float acc[4][4][4])
{
    const uint32_t* Ah = s;
    const uint32_t* Al = s + ARR_B / 4;
    const uint32_t* Bh = s + 2 * ARR_B / 4;
    const uint32_t* Bl = s + 3 * ARR_B / 4;
#pragma unroll
    for (int ks = 0; ks < 2; ks++) {
        const int w0 = lc + ks * 8;
        const int w1 = lc + 4 + ks * 8;
        uint32_t bh[4][2], bl[4][2];
#pragma unroll
        for (int ni = 0; ni < 4; ni++) {
            int r = (n_w + ni * 8 + lr) * RS_U32;
            bh[ni][0] = Bh[r + w0]; bh[ni][1] = Bh[r + w1];
            bl[ni][0] = Bl[r + w0]; bl[ni][1] = Bl[r + w1];
        }
#pragma unroll
        for (int mi = 0; mi < 4; mi++) {
            int r0 = (m_w + mi * 16 + lr) * RS_U32;
            int r1 = r0 + 8 * RS_U32;
            uint32_t ah[4] = {Ah[r0 + w0], Ah[r1 + w0], Ah[r0 + w1], Ah[r1 + w1]};
            uint32_t al[4] = {Al[r0 + w0], Al[r1 + w0], Al[r0 + w1], Al[r1 + w1]};
#pragma unroll
            for (int ni = 0; ni < 4; ni++) {
                mma_bf16(acc[mi][ni], ah, bh[ni]);
                mma_bf16(acc[mi][ni], ah, bl[ni]);
                mma_bf16(acc[mi][ni], al, bh[ni]);
            }
        }
    }
}

__device__ __forceinline__ void gemm_body_mma(
    const bf16* __restrict__ Ah0, const bf16* __restrict__ Al0,
    const bf16* __restrict__ Bh0, const bf16* __restrict__ Bl0,
    const float* __restrict__ bias, float* __restrict__ C,
    int m0, int n0)
{
    extern __shared__ char sm[];
    const int tid  = threadIdx.x;
    const int wid  = tid >> 5;
    const int lane = tid & 31;
    const int lr = lane >> 2, lc = lane & 3;
    const int m_w = (wid & 1) * 64;
    const int n_w = (wid >> 1) * 32;

    const bf16* Ah = Ah0 + (size_t)m0 * HIDDEN;
    const bf16* Al = Al0 + (size_t)m0 * HIDDEN;
    const bf16* Bh = Bh0 + (size_t)n0 * HIDDEN;
    const bf16* Bl = Bl0 + (size_t)n0 * HIDDEN;

    float acc[4][4][4];
#pragma unroll
    for (int i = 0; i < 4; i++)
#pragma unroll
        for (int j = 0; j < 4; j++)
#pragma unroll
            for (int k = 0; k < 4; k++) acc[i][j][k] = 0.0f;

    const uint32_t sb = smem_u32(sm);
    g_load_stage(sb, Ah, Al, Bh, Bl, 0, tid);
    CP_COMMIT();

    for (int c = 0; c < NCHK; c++) {
        if (c + 1 < NCHK) {
            g_load_stage(sb + ((c + 1) & 1) * STG_B, Ah, Al, Bh, Bl,
                         (c + 1) * KCH, tid);
            CP_COMMIT();
            CP_WAIT1();
        } else {
            CP_WAIT0();
        }
        __syncthreads();
        g_compute((const uint32_t*)(sm + (c & 1) * STG_B), m_w, n_w, lr, lc, acc);
        __syncthreads();
    }

    // Epilogue: bias + store
#pragma unroll
    for (int mi = 0; mi < 4; mi++) {
#pragma unroll
        for (int ni = 0; ni < 4; ni++) {
            int row = m0 + m_w + mi * 16 + lr;
            int col = n0 + n_w + ni * 8 + lc * 2;
            float b0 = bias[col], b1 = bias[col + 1];
            float2 v0 = make_float2(acc[mi][ni][0] + b0, acc[mi][ni][1] + b1);
            float2 v1 = make_float2(acc[mi][ni][2] + b0, acc[mi][ni][3] + b1);
            *(float2*)&C[(size_t)row * HIDDEN + col]       = v0;
            *(float2*)&C[(size_t)(row + 8) * HIDDEN + col] = v1;
        }
    }
}

__global__ __launch_bounds__(256) void gemm_qkv_kernel(
    const float* __restrict__ bq, const float* __restrict__ bk,
    const float* __restrict__ bv)
{
    const bf16* Bh; const bf16* Bl; const float* bias; float* C;
    if (blockIdx.z == 0)      { Bh = g_wth;                         Bl = g_wtl;                         bias = bq; C = g_q; }
    else if (blockIdx.z == 1) { Bh = g_wth + 1 * HIDDEN * HIDDEN;   Bl = g_wtl + 1 * HIDDEN * HIDDEN;   bias = bk; C = g_k; }
    else                      { Bh = g_wth + 2 * HIDDEN * HIDDEN;   Bl = g_wtl + 2 * HIDDEN * HIDDEN;   bias = bv; C = g_v; }
    gemm_body_mma(g_xh, g_xl, Bh, Bl, bias, C, blockIdx.y * 128, blockIdx.x * 128);
}

__global__ __launch_bounds__(256) void gemm_o_kernel(
    const float* __restrict__ bo, float* __restrict__ out)
{
    gemm_body_mma(g_aoh, g_aol,
                  g_wth + 3 * HIDDEN * HIDDEN, g_wtl + 3 * HIDDEN * HIDDEN,
                  bo, out, blockIdx.y * 128, blockIdx.x * 128);
}

// ---------------- fp32 flash attention (proven, unchanged) -------------------
#define ATT_SMEM (4 * 64 * 68 * 4)

__global__ __launch_bounds__(256) void attn_kernel()
{
    extern __shared__ float smf[];
    float (*Qs)[68] = (float(*)[68])(smf);
    float (*Ks)[68] = (float(*)[68])(smf + 64 * 68);
    float (*Vt)[68] = (float(*)[68])(smf + 2 * 64 * 68);
    float (*Ps)[68] = (float(*)[68])(smf + 3 * 64 * 68);

    const int tid = threadIdx.x;
    const int tx = tid & 15;
    const int ty = tid >> 4;
    const int q0 = blockIdx.x * 64;
    const int h  = blockIdx.y;
    const int b  = blockIdx.z;
    const size_t base = (size_t)b * SEQ * HIDDEN + (size_t)h * HD;

#pragma unroll
    for (int l = 0; l < 4; l++) {
        int fi = tid + 256 * l;
        int r  = fi >> 4;
        int d4 = (fi & 15) << 2;
        *(float4*)&Qs[r][d4] =
            *(const float4*)&g_q[base + (size_t)(q0 + r) * HIDDEN + d4];
    }

    float o[4][4];
    float mrow[4], lrow[4];
#pragma unroll
    for (int i = 0; i < 4; i++) {
        mrow[i] = -1e30f; lrow[i] = 0.0f;
#pragma unroll
        for (int j = 0; j < 4; j++) o[i][j] = 0.0f;
    }

    for (int kt = 0; kt < SEQ; kt += 64) {
        __syncthreads();
#pragma unroll
        for (int l = 0; l < 4; l++) {
            int fi = tid + 256 * l;
            int r  = fi >> 4;
            int d4 = (fi & 15) << 2;
            *(float4*)&Ks[r][d4] =
                *(const float4*)&g_k[base + (size_t)(kt + r) * HIDDEN + d4];
        }
#pragma unroll
        for (int p = 0; p < 16; p++) {
            int fi = tid + 256 * p;
            int c  = fi >> 6;
            int d  = fi & 63;
            Vt[d][c] = g_v[base + (size_t)(kt + c) * HIDDEN + d];
        }
        __syncthreads();

        float s[4][4];
#pragma unroll
        for (int i = 0; i < 4; i++)
#pragma unroll
            for (int j = 0; j < 4; j++) s[i][j] = 0.0f;

#pragma unroll
        for (int d = 0; d < 64; d += 4) {
            float4 av[4], bv[4];
#pragma unroll
            for (int i = 0; i < 4; i++) av[i] = *(const float4*)&Qs[ty + 16 * i][d];
#pragma unroll
            for (int j = 0; j < 4; j++) bv[j] = *(const float4*)&Ks[tx + 16 * j][d];
#pragma unroll
            for (int i = 0; i < 4; i++)
#pragma unroll
                for (int j = 0; j < 4; j++) {
                    s[i][j] = fmaf(av[i].x, bv[j].x, s[i][j]);
                    s[i][j] = fmaf(av[i].y, bv[j].y, s[i][j]);
                    s[i][j] = fmaf(av[i].z, bv[j].z, s[i][j]);
                    s[i][j] = fmaf(av[i].w, bv[j].w, s[i][j]);
                }
        }

#pragma unroll
        for (int i = 0; i < 4; i++) {
            float tmax = -1e30f;
#pragma unroll
            for (int j = 0; j < 4; j++) {
                s[i][j] *= 0.125f;
                tmax = fmaxf(tmax, s[i][j]);
            }
#pragma unroll
            for (int off = 8; off >= 1; off >>= 1)
                tmax = fmaxf(tmax, __shfl_xor_sync(0xffffffffu, tmax, off));

            float mn = fmaxf(mrow[i], tmax);
            float corr = __expf(mrow[i] - mn);
            mrow[i] = mn;
            lrow[i] *= corr;
#pragma unroll
            for (int j = 0; j < 4; j++) o[i][j] *= corr;

            float ps = 0.0f;
#pragma unroll
            for (int j = 0; j < 4; j++) {
                float p = __expf(s[i][j] - mn);
                ps += p;
                Ps[ty + 16 * i][tx + 16 * j] = p;
            }
#pragma unroll
            for (int off = 8; off >= 1; off >>= 1)
                ps += __shfl_xor_sync(0xffffffffu, ps, off);
            lrow[i] += ps;
        }
        __syncthreads();

#pragma unroll
        for (int c = 0; c < 64; c += 4) {
            float4 av[4], bv[4];
#pragma unroll
            for (int i = 0; i < 4; i++) av[i] = *(const float4*)&Ps[ty + 16 * i][c];
#pragma unroll
            for (int j = 0; j < 4; j++) bv[j] = *(const float4*)&Vt[tx + 16 * j][c];
#pragma unroll
            for (int i = 0; i < 4; i++)
#pragma unroll
                for (int j = 0; j < 4; j++) {
                    o[i][j] = fmaf(av[i].x, bv[j].x, o[i][j]);
                    o[i][j] = fmaf(av[i].y, bv[j].y, o[i][j]);
                    o[i][j] = fmaf(av[i].z, bv[j].z, o[i][j]);
                    o[i][j] = fmaf(av[i].w, bv[j].w, o[i][j]);
                }
        }
    }

#pragma unroll
    for (int i = 0; i < 4; i++) {
        float inv = 1.0f / lrow[i];
#pragma unroll
        for (int j = 0; j < 4; j++) {
            g_ao[base + (size_t)(q0 + ty + 16 * i) * HIDDEN + tx + 16 * j] =
                o[i][j] * inv;
        }
    }
}

// ---------------------------------------------------------------------------
extern "C" void kernel_launch(void* const* d_in, const int* in_sizes, int n_in,
                              void* d_out, int out_size)
{
    const float* x  = (const float*)d_in[0];
    const float* Wq = (const float*)d_in[1];
    const float* bq = (const float*)d_in[2];
    const float* Wk = (const float*)d_in[3];
    const float* bk = (const float*)d_in[4];
    const float* Wv = (const float*)d_in[5];
    const float* bv = (const float*)d_in[6];
    const float* Wo = (const float*)d_in[7];
    const float* bo = (const float*)d_in[8];
    float* out = (float*)d_out;

    static int attr_set = 0;
    if (!attr_set) {
        cudaFuncSetAttribute(gemm_qkv_kernel,
                             cudaFuncAttributeMaxDynamicSharedMemorySize, GSMEM);
        cudaFuncSetAttribute(gemm_o_kernel,
                             cudaFuncAttributeMaxDynamicSharedMemorySize, GSMEM);
        cudaFuncSetAttribute(attn_kernel,
                             cudaFuncAttributeMaxDynamicSharedMemorySize, ATT_SMEM);
        attr_set = 1;
    }

    split_x_kernel<<<MTOT * HIDDEN / 1024, 256>>>(x);
    wtrans_kernel<<<dim3(32, 32, 4), dim3(32, 8)>>>(Wq, Wk, Wv, Wo);
    gemm_qkv_kernel<<<dim3(HIDDEN / 128, MTOT / 128, 3), 256, GSMEM>>>(bq, bk, bv);
    attn_kernel<<<dim3(SEQ / 64, HEADS, BATCH), 256, ATT_SMEM>>>();
    split_ao_kernel<<<MTOT * HIDDEN / 1024, 256>>>();
    gemm_o_kernel<<<dim3(HIDDEN / 128, MTOT / 128, 1), 256, GSMEM>>>(bo, out);
}

// round 4
// speedup vs baseline: 2.0988x; 1.6255x over previous
#include <cuda_runtime.h>
#include <cuda_bf16.h>
#include <cstdint>

#define HIDDEN 1024
#define SEQ    2048
#define BATCH  2
#define HEADS  16
#define HD     64
#define MTOT   (BATCH*SEQ)   // 4096

typedef __nv_bfloat16 bf16;

// Scale folded into Q projection: 1/sqrt(64) * log2(e)
#define SCALE_Q (0.125f * 1.4426950408889634f)

// ---------------- scratch (device globals) -----------------------------------
__device__ bf16 g_xh [MTOT*HIDDEN];
__device__ bf16 g_xl [MTOT*HIDDEN];
__device__ bf16 g_qh [MTOT*HIDDEN];
__device__ bf16 g_ql [MTOT*HIDDEN];
__device__ bf16 g_kh [MTOT*HIDDEN];
__device__ bf16 g_kl [MTOT*HIDDEN];
__device__ bf16 g_vh [MTOT*HIDDEN];
__device__ bf16 g_vl [MTOT*HIDDEN];
__device__ bf16 g_aoh[MTOT*HIDDEN];
__device__ bf16 g_aol[MTOT*HIDDEN];
__device__ bf16 g_wth[4*HIDDEN*HIDDEN];   // W^T hi, [n][k]
__device__ bf16 g_wtl[4*HIDDEN*HIDDEN];   // W^T lo

// ---------------- helpers ----------------------------------------------------
__device__ __forceinline__ uint32_t smem_u32(const void* p) {
    uint32_t a;
    asm("{ .reg .u64 t; cvta.to.shared.u64 t, %1; cvt.u32.u64 %0, t; }"
        : "=r"(a) : "l"(p));
    return a;
}
__device__ __forceinline__ void cpasync16(uint32_t dst, const void* src) {
    asm volatile("cp.async.cg.shared.global [%0], [%1], 16;"
                 :: "r"(dst), "l"(src));
}
#define CP_COMMIT() asm volatile("cp.async.commit_group;" ::: "memory")
#define CP_WAIT1()  asm volatile("cp.async.wait_group 1;"  ::: "memory")
#define CP_WAIT0()  asm volatile("cp.async.wait_group 0;"  ::: "memory")

__device__ __forceinline__ void mma_bf16(float* c, const uint32_t* a,
                                         const uint32_t* b) {
    asm volatile(
        "mma.sync.aligned.m16n8k16.row.col.f32.bf16.bf16.f32 "
        "{%0,%1,%2,%3}, {%4,%5,%6,%7}, {%8,%9}, {%0,%1,%2,%3};"
        : "+f"(c[0]), "+f"(c[1]), "+f"(c[2]), "+f"(c[3])
        : "r"(a[0]), "r"(a[1]), "r"(a[2]), "r"(a[3]), "r"(b[0]), "r"(b[1]));
}
__device__ __forceinline__ void ldsm4(uint32_t* r, uint32_t addr) {
    asm volatile("ldmatrix.sync.aligned.m8n8.x4.shared.b16 {%0,%1,%2,%3}, [%4];"
                 : "=r"(r[0]), "=r"(r[1]), "=r"(r[2]), "=r"(r[3]) : "r"(addr));
}
__device__ __forceinline__ void ldsm4t(uint32_t* r, uint32_t addr) {
    asm volatile("ldmatrix.sync.aligned.m8n8.x4.trans.shared.b16 {%0,%1,%2,%3}, [%4];"
                 : "=r"(r[0]), "=r"(r[1]), "=r"(r[2]), "=r"(r[3]) : "r"(addr));
}
__device__ __forceinline__ float ex2(float x) {
    float y;
    asm("ex2.approx.ftz.f32 %0, %1;" : "=f"(y) : "f"(x));
    return y;
}
__device__ __forceinline__ uint32_t packbf(float a, float b) {
    __nv_bfloat162 t = __floats2bfloat162_rn(a, b);   // .x = a (low)
    return *(uint32_t*)&t;
}

// ---------------- prep: split fp32 -> bf16 hi/lo -----------------------------
__device__ __forceinline__ void split4(float4 v, ushort4& hv, ushort4& lv) {
    bf16 h0 = __float2bfloat16(v.x), h1 = __float2bfloat16(v.y);
    bf16 h2 = __float2bfloat16(v.z), h3 = __float2bfloat16(v.w);
    hv.x = __bfloat16_as_ushort(h0); hv.y = __bfloat16_as_ushort(h1);
    hv.z = __bfloat16_as_ushort(h2); hv.w = __bfloat16_as_ushort(h3);
    lv.x = __bfloat16_as_ushort(__float2bfloat16(v.x - __bfloat162float(h0)));
    lv.y = __bfloat16_as_ushort(__float2bfloat16(v.y - __bfloat162float(h1)));
    lv.z = __bfloat16_as_ushort(__float2bfloat16(v.z - __bfloat162float(h2)));
    lv.w = __bfloat16_as_ushort(__float2bfloat16(v.w - __bfloat162float(h3)));
}
__global__ __launch_bounds__(256) void split_x_kernel(const float* __restrict__ src) {
    int i = (blockIdx.x * 256 + threadIdx.x) * 4;
    ushort4 hv, lv;
    split4(*(const float4*)&src[i], hv, lv);
    *(ushort4*)&g_xh[i] = hv;
    *(ushort4*)&g_xl[i] = lv;
}

// ---------------- transpose + split weights ----------------------------------
__global__ __launch_bounds__(256) void wtrans_kernel(
    const float* __restrict__ W0, const float* __restrict__ W1,
    const float* __restrict__ W2, const float* __restrict__ W3)
{
    __shared__ float t[32][33];
    const float* W = (blockIdx.z == 0) ? W0 : (blockIdx.z == 1) ? W1
                   : (blockIdx.z == 2) ? W2 : W3;
    bf16* oh = g_wth + (size_t)blockIdx.z * HIDDEN * HIDDEN;
    bf16* ol = g_wtl + (size_t)blockIdx.z * HIDDEN * HIDDEN;
    int n0 = blockIdx.x * 32, k0 = blockIdx.y * 32;
    int tx = threadIdx.x, ty = threadIdx.y;
#pragma unroll
    for (int i = 0; i < 4; i++)
        t[ty + 8 * i][tx] = W[(size_t)(k0 + ty + 8 * i) * HIDDEN + n0 + tx];
    __syncthreads();
#pragma unroll
    for (int i = 0; i < 4; i++) {
        float v = t[tx][ty + 8 * i];
        bf16 h = __float2bfloat16(v);
        bf16 l = __float2bfloat16(v - __bfloat162float(h));
        size_t o = (size_t)(n0 + ty + 8 * i) * HIDDEN + k0 + tx;
        oh[o] = h;
        ol[o] = l;
    }
}

// ---------------- bf16x3 GEMM via mma.sync ------------------------------------
#define KCH    32
#define NCHK   (HIDDEN / KCH)   // 32
#define RS_U32 20
#define ARR_B  (128 * 40 * 2)        // 10240 bytes per array
#define STG_B  (4 * ARR_B)           // 40960 bytes
#define GSMEM  (2 * STG_B)           // 81920 bytes

__device__ __forceinline__ void g_load_stage(
    uint32_t sbase, const bf16* __restrict__ Ah, const bf16* __restrict__ Al,
    const bf16* __restrict__ Bh, const bf16* __restrict__ Bl, int ko, int tid)
{
#pragma unroll
    for (int l = 0; l < 2; l++) {
        int fi  = tid + 256 * l;
        int row = fi >> 2;
        int w   = fi & 3;
        uint32_t so = sbase + (uint32_t)(row * 80 + w * 16);
        size_t   go = (size_t)row * HIDDEN + ko + w * 8;
        cpasync16(so + 0 * ARR_B, Ah + go);
        cpasync16(so + 1 * ARR_B, Al + go);
        cpasync16(so + 2 * ARR_B, Bh + go);
        cpasync16(so + 3 * ARR_B, Bl + go);
    }
}

__device__ __forceinline__ void g_compute(
    const uint32_t* __restrict__ s, int m_w, int n_w, int lr, int lc,
    float acc[4][4][4])
{
    const uint32_t* Ah = s;
    const uint32_t* Al = s + ARR_B / 4;
    const uint32_t* Bh = s + 2 * ARR_B / 4;
    const uint32_t* Bl = s + 3 * ARR_B / 4;
#pragma unroll
    for (int ks = 0; ks < 2; ks++) {
        const int w0 = lc + ks * 8;
        const int w1 = lc + 4 + ks * 8;
        uint32_t bh[4][2], bl[4][2];
#pragma unroll
        for (int ni = 0; ni < 4; ni++) {
            int r = (n_w + ni * 8 + lr) * RS_U32;
            bh[ni][0] = Bh[r + w0]; bh[ni][1] = Bh[r + w1];
            bl[ni][0] = Bl[r + w0]; bl[ni][1] = Bl[r + w1];
        }
#pragma unroll
        for (int mi = 0; mi < 4; mi++) {
            int r0 = (m_w + mi * 16 + lr) * RS_U32;
            int r1 = r0 + 8 * RS_U32;
            uint32_t ah[4] = {Ah[r0 + w0], Ah[r1 + w0], Ah[r0 + w1], Ah[r1 + w1]};
            uint32_t al[4] = {Al[r0 + w0], Al[r1 + w0], Al[r0 + w1], Al[r1 + w1]};
#pragma unroll
            for (int ni = 0; ni < 4; ni++) {
                mma_bf16(acc[mi][ni], ah, bh[ni]);
                mma_bf16(acc[mi][ni], ah, bl[ni]);
                mma_bf16(acc[mi][ni], al, bh[ni]);
            }
        }
    }
}

// Fused compute core; epilogue selected by Cf (fp32) vs Ch/Cl (split bf16).
__device__ __forceinline__ void gemm_body_mma(
    const bf16* __restrict__ Ah0, const bf16* __restrict__ Al0,
    const bf16* __restrict__ Bh0, const bf16* __restrict__ Bl0,
    const float* __restrict__ bias,
    float* __restrict__ Cf, bf16* __restrict__ Ch, bf16* __restrict__ Cl,
    float scale, int m0, int n0)
{
    extern __shared__ char sm[];
    const int tid  = threadIdx.x;
    const int wid  = tid >> 5;
    const int lane = tid & 31;
    const int lr = lane >> 2, lc = lane & 3;
    const int m_w = (wid & 1) * 64;
    const int n_w = (wid >> 1) * 32;

    const bf16* Ah = Ah0 + (size_t)m0 * HIDDEN;
    const bf16* Al = Al0 + (size_t)m0 * HIDDEN;
    const bf16* Bh = Bh0 + (size_t)n0 * HIDDEN;
    const bf16* Bl = Bl0 + (size_t)n0 * HIDDEN;

    float acc[4][4][4];
#pragma unroll
    for (int i = 0; i < 4; i++)
#pragma unroll
        for (int j = 0; j < 4; j++)
#pragma unroll
            for (int k = 0; k < 4; k++) acc[i][j][k] = 0.0f;

    const uint32_t sb = smem_u32(sm);
    g_load_stage(sb, Ah, Al, Bh, Bl, 0, tid);
    CP_COMMIT();

    for (int c = 0; c < NCHK; c++) {
        if (c + 1 < NCHK) {
            g_load_stage(sb + ((c + 1) & 1) * STG_B, Ah, Al, Bh, Bl,
                         (c + 1) * KCH, tid);
            CP_COMMIT();
            CP_WAIT1();
        } else {
            CP_WAIT0();
        }
        __syncthreads();
        g_compute((const uint32_t*)(sm + (c & 1) * STG_B), m_w, n_w, lr, lc, acc);
        __syncthreads();
    }

#pragma unroll
    for (int mi = 0; mi < 4; mi++) {
#pragma unroll
        for (int ni = 0; ni < 4; ni++) {
            int row = m0 + m_w + mi * 16 + lr;
            int col = n0 + n_w + ni * 8 + lc * 2;
            float b0 = bias[col], b1 = bias[col + 1];
            float v00 = (acc[mi][ni][0] + b0) * scale;
            float v01 = (acc[mi][ni][1] + b1) * scale;
            float v10 = (acc[mi][ni][2] + b0) * scale;
            float v11 = (acc[mi][ni][3] + b1) * scale;
            if (Cf) {
                *(float2*)&Cf[(size_t)row * HIDDEN + col]       = make_float2(v00, v01);
                *(float2*)&Cf[(size_t)(row + 8) * HIDDEN + col] = make_float2(v10, v11);
            } else {
                bf16 h00 = __float2bfloat16(v00), h01 = __float2bfloat16(v01);
                bf16 h10 = __float2bfloat16(v10), h11 = __float2bfloat16(v11);
                *(uint32_t*)&Ch[(size_t)row * HIDDEN + col] =
                    packbf(__bfloat162float(h00), __bfloat162float(h01));
                *(uint32_t*)&Ch[(size_t)(row + 8) * HIDDEN + col] =
                    packbf(__bfloat162float(h10), __bfloat162float(h11));
                *(uint32_t*)&Cl[(size_t)row * HIDDEN + col] =
                    packbf(v00 - __bfloat162float(h00), v01 - __bfloat162float(h01));
                *(uint32_t*)&Cl[(size_t)(row + 8) * HIDDEN + col] =
                    packbf(v10 - __bfloat162float(h10), v11 - __bfloat162float(h11));
            }
        }
    }
}

__global__ __launch_bounds__(256) void gemm_qkv_kernel(
    const float* __restrict__ bq, const float* __restrict__ bk,
    const float* __restrict__ bv)
{
    const bf16* Bh; const bf16* Bl; const float* bias;
    bf16 *Ch, *Cl; float scale;
    if (blockIdx.z == 0) {
        Bh = g_wth; Bl = g_wtl; bias = bq; Ch = g_qh; Cl = g_ql; scale = SCALE_Q;
    } else if (blockIdx.z == 1) {
        Bh = g_wth + 1 * HIDDEN * HIDDEN; Bl = g_wtl + 1 * HIDDEN * HIDDEN;
        bias = bk; Ch = g_kh; Cl = g_kl; scale = 1.0f;
    } else {
        Bh = g_wth + 2 * HIDDEN * HIDDEN; Bl = g_wtl + 2 * HIDDEN * HIDDEN;
        bias = bv; Ch = g_vh; Cl = g_vl; scale = 1.0f;
    }
    gemm_body_mma(g_xh, g_xl, Bh, Bl, bias, nullptr, Ch, Cl, scale,
                  blockIdx.y * 128, blockIdx.x * 128);
}

__global__ __launch_bounds__(256) void gemm_o_kernel(
    const float* __restrict__ bo, float* __restrict__ out)
{
    gemm_body_mma(g_aoh, g_aol,
                  g_wth + 3 * HIDDEN * HIDDEN, g_wtl + 3 * HIDDEN * HIDDEN,
                  bo, out, nullptr, nullptr, 1.0f,
                  blockIdx.y * 128, blockIdx.x * 128);
}

// ---------------- flash attention on mma.sync (bf16 hi/lo) -------------------
// CTA: 128 threads (4 warps), q-tile 64 (warp = 16 rows), key tiles of 64.
// SMEM: Qh,Ql [64][72] + 2 stages x {Kh,Kl,Vh,Vl}[64][72]. Row stride 144B.
#define AT_RSB   144
#define AT_TILEB (64 * AT_RSB)                 // 9216 bytes
#define AT_QOFF  0
#define AT_STG(s) (2 * AT_TILEB + (s) * 4 * AT_TILEB)
#define AT_SMEM  (10 * AT_TILEB)               // 92160 bytes
#define NKT      (SEQ / 64)                    // 32

__device__ __forceinline__ void at_load_kv(uint32_t sdst, size_t gbase,
                                           int kt, int tid)
{
    int row = tid >> 1;
    int c0  = (tid & 1) * 64;
    size_t go = gbase + (size_t)(kt + row) * HIDDEN;
    const char* kh = (const char*)(g_kh + go);
    const char* kl = (const char*)(g_kl + go);
    const char* vh = (const char*)(g_vh + go);
    const char* vl = (const char*)(g_vl + go);
    uint32_t sd = sdst + (uint32_t)(row * AT_RSB + c0);
#pragma unroll
    for (int i = 0; i < 4; i++) {
        cpasync16(sd + 0 * AT_TILEB + i * 16, kh + c0 + i * 16);
        cpasync16(sd + 1 * AT_TILEB + i * 16, kl + c0 + i * 16);
        cpasync16(sd + 2 * AT_TILEB + i * 16, vh + c0 + i * 16);
        cpasync16(sd + 3 * AT_TILEB + i * 16, vl + c0 + i * 16);
    }
}

__global__ __launch_bounds__(128) void attn_mma_kernel()
{
    extern __shared__ char sma[];
    const int tid  = threadIdx.x;
    const int wid  = tid >> 5;
    const int lane = tid & 31;
    const int q0 = blockIdx.x * 64;
    const int h  = blockIdx.y;
    const int b  = blockIdx.z;
    const size_t base = (size_t)b * SEQ * HIDDEN + (size_t)h * HD;
    const uint32_t sb = smem_u32(sma);

    // Q tile load (hi+lo)
    {
        int row = tid >> 1;
        int c0  = (tid & 1) * 64;
        size_t go = base + (size_t)(q0 + row) * HIDDEN;
        const char* qh = (const char*)(g_qh + go);
        const char* ql = (const char*)(g_ql + go);
        uint32_t sd = sb + AT_QOFF + (uint32_t)(row * AT_RSB + c0);
#pragma unroll
        for (int i = 0; i < 4; i++) {
            cpasync16(sd + i * 16,             qh + c0 + i * 16);
            cpasync16(sd + AT_TILEB + i * 16,  ql + c0 + i * 16);
        }
    }
    at_load_kv(sb + AT_STG(0), base, 0, tid);
    CP_COMMIT();

    uint32_t qh[4][4], ql[4][4];
    float    s[8][4], o[8][4];
    float m0 = -1e30f, m1 = -1e30f, l0 = 0.0f, l1 = 0.0f;
#pragma unroll
    for (int i = 0; i < 8; i++)
#pragma unroll
        for (int j = 0; j < 4; j++) o[i][j] = 0.0f;

    // ldmatrix lane addressing pieces
    const int lrow8 = (lane & 7) + ((lane >> 3) & 1) * 8;  // A/trans row pattern
    const int lhi16 = (lane >> 4);                          // 0/1 -> +8 cols

    for (int t = 0; t < NKT; t++) {
        if (t + 1 < NKT) {
            at_load_kv(sb + AT_STG((t + 1) & 1), base, (t + 1) * 64, tid);
            CP_COMMIT();
            CP_WAIT1();
        } else {
            CP_WAIT0();
        }
        __syncthreads();

        if (t == 0) {
            // load Q fragments (A-frag) once
#pragma unroll
            for (int j = 0; j < 4; j++) {
                uint32_t a = sb + AT_QOFF +
                    (uint32_t)((wid * 16 + lrow8) * AT_RSB + j * 32 + lhi16 * 16);
                ldsm4(qh[j], a);
                ldsm4(ql[j], a + AT_TILEB);
            }
        }

        const uint32_t st  = sb + AT_STG(t & 1);
        const uint32_t skh = st + 0 * AT_TILEB;
        const uint32_t skl = st + 1 * AT_TILEB;
        const uint32_t svh = st + 2 * AT_TILEB;
        const uint32_t svl = st + 3 * AT_TILEB;

        // ---- S = Qhat · K^T (3-way split) ----
#pragma unroll
        for (int nt = 0; nt < 8; nt++) {
#pragma unroll
            for (int j = 0; j < 4; j++) s[nt][j] = 0.0f;
#pragma unroll
            for (int g = 0; g < 2; g++) {
                uint32_t kb[4], klb[4];
                uint32_t a = skh +
                    (uint32_t)((nt * 8 + (lane & 7)) * AT_RSB + g * 64 + (lane >> 3) * 16);
                ldsm4(kb,  a);
                ldsm4(klb, a + AT_TILEB);   // skl = skh + AT_TILEB
                mma_bf16(s[nt], qh[2 * g],     kb);
                mma_bf16(s[nt], qh[2 * g],     klb);
                mma_bf16(s[nt], ql[2 * g],     kb);
                mma_bf16(s[nt], qh[2 * g + 1], kb + 2);
                mma_bf16(s[nt], qh[2 * g + 1], klb + 2);
                mma_bf16(s[nt], ql[2 * g + 1], kb + 2);
            }
        }

        // ---- online softmax (base-2; scale folded into Q) ----
        float tm0 = -1e30f, tm1 = -1e30f;
#pragma unroll
        for (int nt = 0; nt < 8; nt++) {
            tm0 = fmaxf(tm0, fmaxf(s[nt][0], s[nt][1]));
            tm1 = fmaxf(tm1, fmaxf(s[nt][2], s[nt][3]));
        }
        tm0 = fmaxf(tm0, __shfl_xor_sync(0xffffffffu, tm0, 1));
        tm0 = fmaxf(tm0, __shfl_xor_sync(0xffffffffu, tm0, 2));
        tm1 = fmaxf(tm1, __shfl_xor_sync(0xffffffffu, tm1, 1));
        tm1 = fmaxf(tm1, __shfl_xor_sync(0xffffffffu, tm1, 2));

        float mn0 = fmaxf(m0, tm0), mn1 = fmaxf(m1, tm1);
        float cr0 = ex2(m0 - mn0),  cr1 = ex2(m1 - mn1);
        m0 = mn0; m1 = mn1;

        uint32_t ah[4][4], al[4][4];
        float rs0 = 0.0f, rs1 = 0.0f;
#pragma unroll
        for (int nt = 0; nt < 8; nt++) {
            float p0 = ex2(s[nt][0] - mn0);
            float p1 = ex2(s[nt][1] - mn0);
            float p2 = ex2(s[nt][2] - mn1);
            float p3 = ex2(s[nt][3] - mn1);
            rs0 += p0 + p1;
            rs1 += p2 + p3;
            bf16 h0 = __float2bfloat16(p0), h1 = __float2bfloat16(p1);
            bf16 h2 = __float2bfloat16(p2), h3 = __float2bfloat16(p3);
            int kg = nt >> 1, hf = (nt & 1) * 2;
            ah[kg][hf + 0] = packbf(__bfloat162float(h0), __bfloat162float(h1));
            ah[kg][hf + 1] = packbf(__bfloat162float(h2), __bfloat162float(h3));
            al[kg][hf + 0] = packbf(p0 - __bfloat162float(h0), p1 - __bfloat162float(h1));
            al[kg][hf + 1] = packbf(p2 - __bfloat162float(h2), p3 - __bfloat162float(h3));
        }
        rs0 += __shfl_xor_sync(0xffffffffu, rs0, 1);
        rs0 += __shfl_xor_sync(0xffffffffu, rs0, 2);
        rs1 += __shfl_xor_sync(0xffffffffu, rs1, 1);
        rs1 += __shfl_xor_sync(0xffffffffu, rs1, 2);
        l0 = l0 * cr0 + rs0;
        l1 = l1 * cr1 + rs1;
#pragma unroll
        for (int nt = 0; nt < 8; nt++) {
            o[nt][0] *= cr0; o[nt][1] *= cr0;
            o[nt][2] *= cr1; o[nt][3] *= cr1;
        }

        // ---- O += P · V (3-way split), V^T via ldmatrix.trans ----
#pragma unroll
        for (int dp = 0; dp < 4; dp++) {
#pragma unroll
            for (int kg = 0; kg < 4; kg++) {
                uint32_t vb[4], vlb[4];
                uint32_t a = svh +
                    (uint32_t)((kg * 16 + lrow8) * AT_RSB + dp * 32 + lhi16 * 16);
                ldsm4t(vb,  a);
                ldsm4t(vlb, a + AT_TILEB);   // svl = svh + AT_TILEB
                mma_bf16(o[2 * dp],     ah[kg], vb);
                mma_bf16(o[2 * dp],     al[kg], vb);
                mma_bf16(o[2 * dp],     ah[kg], vlb);
                mma_bf16(o[2 * dp + 1], ah[kg], vb + 2);
                mma_bf16(o[2 * dp + 1], al[kg], vb + 2);
                mma_bf16(o[2 * dp + 1], ah[kg], vlb + 2);
            }
        }
        __syncthreads();
    }

    // ---- epilogue: normalize, split hi/lo, store ----
    float inv0 = 1.0f / l0, inv1 = 1.0f / l1;
    int r0 = q0 + wid * 16 + (lane >> 2);
    int cbase = (lane & 3) * 2;
#pragma unroll
    for (int nt = 0; nt < 8; nt++) {
        int col = nt * 8 + cbase;
        float v00 = o[nt][0] * inv0, v01 = o[nt][1] * inv0;
        float v10 = o[nt][2] * inv1, v11 = o[nt][3] * inv1;
        bf16 h00 = __float2bfloat16(v00), h01 = __float2bfloat16(v01);
        bf16 h10 = __float2bfloat16(v10), h11 = __float2bfloat16(v11);
        size_t o0 = base + (size_t)r0 * HIDDEN + col;
        size_t o1 = base + (size_t)(r0 + 8) * HIDDEN + col;
        *(uint32_t*)&g_aoh[o0] = packbf(__bfloat162float(h00), __bfloat162float(h01));
        *(uint32_t*)&g_aoh[o1] = packbf(__bfloat162float(h10), __bfloat162float(h11));
        *(uint32_t*)&g_aol[o0] = packbf(v00 - __bfloat162float(h00), v01 - __bfloat162float(h01));
        *(uint32_t*)&g_aol[o1] = packbf(v10 - __bfloat162float(h10), v11 - __bfloat162float(h11));
    }
}

// ---------------------------------------------------------------------------
extern "C" void kernel_launch(void* const* d_in, const int* in_sizes, int n_in,
                              void* d_out, int out_size)
{
    const float* x  = (const float*)d_in[0];
    const float* Wq = (const float*)d_in[1];
    const float* bq = (const float*)d_in[2];
    const float* Wk = (const float*)d_in[3];
    const float* bk = (const float*)d_in[4];
    const float* Wv = (const float*)d_in[5];
    const float* bv = (const float*)d_in[6];
    const float* Wo = (const float*)d_in[7];
    const float* bo = (const float*)d_in[8];
    float* out = (float*)d_out;

    static int attr_set = 0;
    if (!attr_set) {
        cudaFuncSetAttribute(gemm_qkv_kernel,
                             cudaFuncAttributeMaxDynamicSharedMemorySize, GSMEM);
        cudaFuncSetAttribute(gemm_o_kernel,
                             cudaFuncAttributeMaxDynamicSharedMemorySize, GSMEM);
        cudaFuncSetAttribute(attn_mma_kernel,
                             cudaFuncAttributeMaxDynamicSharedMemorySize, AT_SMEM);
        attr_set = 1;
    }

    split_x_kernel<<<MTOT * HIDDEN / 1024, 256>>>(x);
    wtrans_kernel<<<dim3(32, 32, 4), dim3(32, 8)>>>(Wq, Wk, Wv, Wo);
    gemm_qkv_kernel<<<dim3(HIDDEN / 128, MTOT / 128, 3), 256, GSMEM>>>(bq, bk, bv);
    attn_mma_kernel<<<dim3(SEQ / 64, HEADS, BATCH), 128, AT_SMEM>>>();
    gemm_o_kernel<<<dim3(HIDDEN / 128, MTOT / 128, 1), 256, GSMEM>>>(bo, out);
}

// round 6
// speedup vs baseline: 2.4316x; 1.1586x over previous
#include <cuda_runtime.h>
#include <cuda_bf16.h>
#include <cstdint>

#define HIDDEN 1024
#define SEQ    2048
#define BATCH  2
#define HEADS  16
#define HD     64
#define MTOT   (BATCH*SEQ)   // 4096

typedef __nv_bfloat16 bf16;

// Scale folded into Q projection: 1/sqrt(64) * log2(e)
#define SCALE_Q (0.125f * 1.4426950408889634f)

// ---------------- scratch (device globals) -----------------------------------
__device__ bf16 g_xh [MTOT*HIDDEN];
__device__ bf16 g_xl [MTOT*HIDDEN];
__device__ bf16 g_qh [MTOT*HIDDEN];
__device__ bf16 g_ql [MTOT*HIDDEN];
__device__ bf16 g_kh [MTOT*HIDDEN];
__device__ bf16 g_kl [MTOT*HIDDEN];
__device__ bf16 g_vh [MTOT*HIDDEN];
__device__ bf16 g_vl [MTOT*HIDDEN];
__device__ bf16 g_aoh[MTOT*HIDDEN];
__device__ bf16 g_aol[MTOT*HIDDEN];
__device__ bf16 g_wth[4*HIDDEN*HIDDEN];   // W^T hi, [n][k]
__device__ bf16 g_wtl[4*HIDDEN*HIDDEN];   // W^T lo

// ---------------- helpers ----------------------------------------------------
__device__ __forceinline__ uint32_t smem_u32(const void* p) {
    uint32_t a;
    asm("{ .reg .u64 t; cvta.to.shared.u64 t, %1; cvt.u32.u64 %0, t; }"
        : "=r"(a) : "l"(p));
    return a;
}
__device__ __forceinline__ void cpasync16(uint32_t dst, const void* src) {
    asm volatile("cp.async.cg.shared.global [%0], [%1], 16;"
                 :: "r"(dst), "l"(src));
}
#define CP_COMMIT() asm volatile("cp.async.commit_group;" ::: "memory")
#define CP_WAIT1()  asm volatile("cp.async.wait_group 1;"  ::: "memory")
#define CP_WAIT0()  asm volatile("cp.async.wait_group 0;"  ::: "memory")

__device__ __forceinline__ void mma_bf16(float* c, const uint32_t* a,
                                         const uint32_t* b) {
    asm volatile(
        "mma.sync.aligned.m16n8k16.row.col.f32.bf16.bf16.f32 "
        "{%0,%1,%2,%3}, {%4,%5,%6,%7}, {%8,%9}, {%0,%1,%2,%3};"
        : "+f"(c[0]), "+f"(c[1]), "+f"(c[2]), "+f"(c[3])
        : "r"(a[0]), "r"(a[1]), "r"(a[2]), "r"(a[3]), "r"(b[0]), "r"(b[1]));
}
__device__ __forceinline__ void ldsm4(uint32_t* r, uint32_t addr) {
    asm volatile("ldmatrix.sync.aligned.m8n8.x4.shared.b16 {%0,%1,%2,%3}, [%4];"
                 : "=r"(r[0]), "=r"(r[1]), "=r"(r[2]), "=r"(r[3]) : "r"(addr));
}
__device__ __forceinline__ void ldsm4t(uint32_t* r, uint32_t addr) {
    asm volatile("ldmatrix.sync.aligned.m8n8.x4.trans.shared.b16 {%0,%1,%2,%3}, [%4];"
                 : "=r"(r[0]), "=r"(r[1]), "=r"(r[2]), "=r"(r[3]) : "r"(addr));
}
__device__ __forceinline__ float ex2(float x) {
    float y;
    asm("ex2.approx.ftz.f32 %0, %1;" : "=f"(y) : "f"(x));
    return y;
}
__device__ __forceinline__ uint32_t packbf(float a, float b) {
    __nv_bfloat162 t = __floats2bfloat162_rn(a, b);   // .x = a (low)
    return *(uint32_t*)&t;
}

// ---------------- prep: split fp32 -> bf16 hi/lo -----------------------------
__device__ __forceinline__ void split4(float4 v, ushort4& hv, ushort4& lv) {
    bf16 h0 = __float2bfloat16(v.x), h1 = __float2bfloat16(v.y);
    bf16 h2 = __float2bfloat16(v.z), h3 = __float2bfloat16(v.w);
    hv.x = __bfloat16_as_ushort(h0); hv.y = __bfloat16_as_ushort(h1);
    hv.z = __bfloat16_as_ushort(h2); hv.w = __bfloat16_as_ushort(h3);
    lv.x = __bfloat16_as_ushort(__float2bfloat16(v.x - __bfloat162float(h0)));
    lv.y = __bfloat16_as_ushort(__float2bfloat16(v.y - __bfloat162float(h1)));
    lv.z = __bfloat16_as_ushort(__float2bfloat16(v.z - __bfloat162float(h2)));
    lv.w = __bfloat16_as_ushort(__float2bfloat16(v.w - __bfloat162float(h3)));
}
__global__ __launch_bounds__(256) void split_x_kernel(const float* __restrict__ src) {
    int i = (blockIdx.x * 256 + threadIdx.x) * 4;
    ushort4 hv, lv;
    split4(*(const float4*)&src[i], hv, lv);
    *(ushort4*)&g_xh[i] = hv;
    *(ushort4*)&g_xl[i] = lv;
}

// ---------------- transpose + split weights ----------------------------------
__global__ __launch_bounds__(256) void wtrans_kernel(
    const float* __restrict__ W0, const float* __restrict__ W1,
    const float* __restrict__ W2, const float* __restrict__ W3)
{
    __shared__ float t[32][33];
    const float* W = (blockIdx.z == 0) ? W0 : (blockIdx.z == 1) ? W1
                   : (blockIdx.z == 2) ? W2 : W3;
    bf16* oh = g_wth + (size_t)blockIdx.z * HIDDEN * HIDDEN;
    bf16* ol = g_wtl + (size_t)blockIdx.z * HIDDEN * HIDDEN;
    int n0 = blockIdx.x * 32, k0 = blockIdx.y * 32;
    int tx = threadIdx.x, ty = threadIdx.y;
#pragma unroll
    for (int i = 0; i < 4; i++)
        t[ty + 8 * i][tx] = W[(size_t)(k0 + ty + 8 * i) * HIDDEN + n0 + tx];
    __syncthreads();
#pragma unroll
    for (int i = 0; i < 4; i++) {
        float v = t[tx][ty + 8 * i];
        bf16 h = __float2bfloat16(v);
        bf16 l = __float2bfloat16(v - __bfloat162float(h));
        size_t o = (size_t)(n0 + ty + 8 * i) * HIDDEN + k0 + tx;
        oh[o] = h;
        ol[o] = l;
    }
}

// ---------------- bf16x3 GEMM via mma.sync ------------------------------------
#define KCH    32
#define NCHK   (HIDDEN / KCH)   // 32
#define RS_U32 20
#define ARR_B  (128 * 40 * 2)        // 10240 bytes per array
#define STG_B  (4 * ARR_B)           // 40960 bytes
#define GSMEM  (2 * STG_B)           // 81920 bytes

__device__ __forceinline__ void g_load_stage(
    uint32_t sbase, const bf16* __restrict__ Ah, const bf16* __restrict__ Al,
    const bf16* __restrict__ Bh, const bf16* __restrict__ Bl, int ko, int tid)
{
#pragma unroll
    for (int l = 0; l < 2; l++) {
        int fi  = tid + 256 * l;
        int row = fi >> 2;
        int w   = fi & 3;
        uint32_t so = sbase + (uint32_t)(row * 80 + w * 16);
        size_t   go = (size_t)row * HIDDEN + ko + w * 8;
        cpasync16(so + 0 * ARR_B, Ah + go);
        cpasync16(so + 1 * ARR_B, Al + go);
        cpasync16(so + 2 * ARR_B, Bh + go);
        cpasync16(so + 3 * ARR_B, Bl + go);
    }
}

__device__ __forceinline__ void g_compute(
    const uint32_t* __restrict__ s, int m_w, int n_w, int lr, int lc,
    float acc[4][4][4])
{
    const uint32_t* Ah = s;
    const uint32_t* Al = s + ARR_B / 4;
    const uint32_t* Bh = s + 2 * ARR_B / 4;
    const uint32_t* Bl = s + 3 * ARR_B / 4;
#pragma unroll
    for (int ks = 0; ks < 2; ks++) {
        const int w0 = lc + ks * 8;
        const int w1 = lc + 4 + ks * 8;
        uint32_t bh[4][2], bl[4][2];
#pragma unroll
        for (int ni = 0; ni < 4; ni++) {
            int r = (n_w + ni * 8 + lr) * RS_U32;
            bh[ni][0] = Bh[r + w0]; bh[ni][1] = Bh[r + w1];
            bl[ni][0] = Bl[r + w0]; bl[ni][1] = Bl[r + w1];
        }
#pragma unroll
        for (int mi = 0; mi < 4; mi++) {
            int r0 = (m_w + mi * 16 + lr) * RS_U32;
            int r1 = r0 + 8 * RS_U32;
            uint32_t ah[4] = {Ah[r0 + w0], Ah[r1 + w0], Ah[r0 + w1], Ah[r1 + w1]};
            uint32_t al[4] = {Al[r0 + w0], Al[r1 + w0], Al[r0 + w1], Al[r1 + w1]};
#pragma unroll
            for (int ni = 0; ni < 4; ni++) {
                mma_bf16(acc[mi][ni], ah, bh[ni]);
                mma_bf16(acc[mi][ni], ah, bl[ni]);
                mma_bf16(acc[mi][ni], al, bh[ni]);
            }
        }
    }
}

// Fused compute core; epilogue selected by Cf (fp32) vs Ch/Cl (split bf16).
__device__ __forceinline__ void gemm_body_mma(
    const bf16* __restrict__ Ah0, const bf16* __restrict__ Al0,
    const bf16* __restrict__ Bh0, const bf16* __restrict__ Bl0,
    const float* __restrict__ bias,
    float* __restrict__ Cf, bf16* __restrict__ Ch, bf16* __restrict__ Cl,
    float scale, int m0, int n0)
{
    extern __shared__ char sm[];
    const int tid  = threadIdx.x;
    const int wid  = tid >> 5;
    const int lane = tid & 31;
    const int lr = lane >> 2, lc = lane & 3;
    const int m_w = (wid & 1) * 64;
    const int n_w = (wid >> 1) * 32;

    const bf16* Ah = Ah0 + (size_t)m0 * HIDDEN;
    const bf16* Al = Al0 + (size_t)m0 * HIDDEN;
    const bf16* Bh = Bh0 + (size_t)n0 * HIDDEN;
    const bf16* Bl = Bl0 + (size_t)n0 * HIDDEN;

    float acc[4][4][4];
#pragma unroll
    for (int i = 0; i < 4; i++)
#pragma unroll
        for (int j = 0; j < 4; j++)
#pragma unroll
            for (int k = 0; k < 4; k++) acc[i][j][k] = 0.0f;

    const uint32_t sb = smem_u32(sm);
    g_load_stage(sb, Ah, Al, Bh, Bl, 0, tid);
    CP_COMMIT();

    for (int c = 0; c < NCHK; c++) {
        if (c + 1 < NCHK) {
            g_load_stage(sb + ((c + 1) & 1) * STG_B, Ah, Al, Bh, Bl,
                         (c + 1) * KCH, tid);
            CP_COMMIT();
            CP_WAIT1();
        } else {
            CP_WAIT0();
        }
        __syncthreads();
        g_compute((const uint32_t*)(sm + (c & 1) * STG_B), m_w, n_w, lr, lc, acc);
        __syncthreads();
    }

#pragma unroll
    for (int mi = 0; mi < 4; mi++) {
#pragma unroll
        for (int ni = 0; ni < 4; ni++) {
            int row = m0 + m_w + mi * 16 + lr;
            int col = n0 + n_w + ni * 8 + lc * 2;
            float b0 = bias[col], b1 = bias[col + 1];
            float v00 = (acc[mi][ni][0] + b0) * scale;
            float v01 = (acc[mi][ni][1] + b1) * scale;
            float v10 = (acc[mi][ni][2] + b0) * scale;
            float v11 = (acc[mi][ni][3] + b1) * scale;
            if (Cf) {
                *(float2*)&Cf[(size_t)row * HIDDEN + col]       = make_float2(v00, v01);
                *(float2*)&Cf[(size_t)(row + 8) * HIDDEN + col] = make_float2(v10, v11);
            } else {
                bf16 h00 = __float2bfloat16(v00), h01 = __float2bfloat16(v01);
                bf16 h10 = __float2bfloat16(v10), h11 = __float2bfloat16(v11);
                *(uint32_t*)&Ch[(size_t)row * HIDDEN + col] =
                    packbf(__bfloat162float(h00), __bfloat162float(h01));
                *(uint32_t*)&Ch[(size_t)(row + 8) * HIDDEN + col] =
                    packbf(__bfloat162float(h10), __bfloat162float(h11));
                *(uint32_t*)&Cl[(size_t)row * HIDDEN + col] =
                    packbf(v00 - __bfloat162float(h00), v01 - __bfloat162float(h01));
                *(uint32_t*)&Cl[(size_t)(row + 8) * HIDDEN + col] =
                    packbf(v10 - __bfloat162float(h10), v11 - __bfloat162float(h11));
            }
        }
    }
}

__global__ __launch_bounds__(256) void gemm_qkv_kernel(
    const float* __restrict__ bq, const float* __restrict__ bk,
    const float* __restrict__ bv)
{
    const bf16* Bh; const bf16* Bl; const float* bias;
    bf16 *Ch, *Cl; float scale;
    if (blockIdx.z == 0) {
        Bh = g_wth; Bl = g_wtl; bias = bq; Ch = g_qh; Cl = g_ql; scale = SCALE_Q;
    } else if (blockIdx.z == 1) {
        Bh = g_wth + 1 * HIDDEN * HIDDEN; Bl = g_wtl + 1 * HIDDEN * HIDDEN;
        bias = bk; Ch = g_kh; Cl = g_kl; scale = 1.0f;
    } else {
        Bh = g_wth + 2 * HIDDEN * HIDDEN; Bl = g_wtl + 2 * HIDDEN * HIDDEN;
        bias = bv; Ch = g_vh; Cl = g_vl; scale = 1.0f;
    }
    gemm_body_mma(g_xh, g_xl, Bh, Bl, bias, nullptr, Ch, Cl, scale,
                  blockIdx.y * 128, blockIdx.x * 128);
}

__global__ __launch_bounds__(256) void gemm_o_kernel(
    const float* __restrict__ bo, float* __restrict__ out)
{
    gemm_body_mma(g_aoh, g_aol,
                  g_wth + 3 * HIDDEN * HIDDEN, g_wtl + 3 * HIDDEN * HIDDEN,
                  bo, out, nullptr, nullptr, 1.0f,
                  blockIdx.y * 128, blockIdx.x * 128);
}

// ---------------- flash attention on mma.sync (bf16 hi/lo) -------------------
// CTA: 256 threads (8 warps), q-tile 128 (warp = 16 rows), key tiles of 64.
// SMEM: Qh,Ql [128][72] + 2 stages x {Kh,Kl,Vh,Vl}[64][72]. Row stride 144B.
// 110592 B/CTA -> 2 CTAs/SM; regs capped at 128 via __launch_bounds__(256,2).
#define AT_RSB   144
#define AT_KTILE (64 * AT_RSB)                  // 9216
#define AT_QTILE (128 * AT_RSB)                 // 18432
#define AT_QOFF  0
#define AT_KV0   (2 * AT_QTILE)                 // 36864
#define AT_STG(s) (AT_KV0 + (s) * 4 * AT_KTILE)
#define AT_SMEM  (AT_KV0 + 8 * AT_KTILE)        // 110592
#define NKT      (SEQ / 64)                     // 32

__device__ __forceinline__ void at_load_kv(uint32_t sdst, size_t gbase,
                                           int kt, int tid)
{
    int row = tid >> 2;               // 0..63
    int c0  = (tid & 3) * 32;         // 0,32,64,96 bytes
    size_t go = gbase + (size_t)(kt + row) * HIDDEN;
    const char* kh = (const char*)(g_kh + go);
    const char* kl = (const char*)(g_kl + go);
    const char* vh = (const char*)(g_vh + go);
    const char* vl = (const char*)(g_vl + go);
    uint32_t sd = sdst + (uint32_t)(row * AT_RSB + c0);
#pragma unroll
    for (int i = 0; i < 2; i++) {
        cpasync16(sd + 0 * AT_KTILE + i * 16, kh + c0 + i * 16);
        cpasync16(sd + 1 * AT_KTILE + i * 16, kl + c0 + i * 16);
        cpasync16(sd + 2 * AT_KTILE + i * 16, vh + c0 + i * 16);
        cpasync16(sd + 3 * AT_KTILE + i * 16, vl + c0 + i * 16);
    }
}

__global__ __launch_bounds__(256, 2) void attn_mma_kernel()
{
    extern __shared__ char sma[];
    const int tid  = threadIdx.x;
    const int wid  = tid >> 5;
    const int lane = tid & 31;
    const int q0 = blockIdx.x * 128;
    const int h  = blockIdx.y;
    const int b  = blockIdx.z;
    const size_t base = (size_t)b * SEQ * HIDDEN + (size_t)h * HD;
    const uint32_t sb = smem_u32(sma);

    // Q tile load (hi+lo): 256 threads cover 128 rows x 128B
    {
        int row = tid >> 1;
        int c0  = (tid & 1) * 64;
        size_t go = base + (size_t)(q0 + row) * HIDDEN;
        const char* qh = (const char*)(g_qh + go);
        const char* ql = (const char*)(g_ql + go);
        uint32_t sd = sb + AT_QOFF + (uint32_t)(row * AT_RSB + c0);
#pragma unroll
        for (int i = 0; i < 4; i++) {
            cpasync16(sd + i * 16,             qh + c0 + i * 16);
            cpasync16(sd + AT_QTILE + i * 16,  ql + c0 + i * 16);
        }
    }
    at_load_kv(sb + AT_STG(0), base, 0, tid);
    CP_COMMIT();

    uint32_t qh[4][4], ql[4][4];
    float    s[8][4], o[8][4];
    float m0 = -1e30f, m1 = -1e30f, l0 = 0.0f, l1 = 0.0f;
#pragma unroll
    for (int i = 0; i < 8; i++)
#pragma unroll
        for (int j = 0; j < 4; j++) o[i][j] = 0.0f;

    const int lrow8 = (lane & 7) + ((lane >> 3) & 1) * 8;
    const int lhi16 = (lane >> 4);

    for (int t = 0; t < NKT; t++) {
        if (t + 1 < NKT) {
            at_load_kv(sb + AT_STG((t + 1) & 1), base, (t + 1) * 64, tid);
            CP_COMMIT();
            CP_WAIT1();
        } else {
            CP_WAIT0();
        }
        __syncthreads();

        if (t == 0) {
#pragma unroll
            for (int j = 0; j < 4; j++) {
                uint32_t a = sb + AT_QOFF +
                    (uint32_t)((wid * 16 + lrow8) * AT_RSB + j * 32 + lhi16 * 16);
                ldsm4(qh[j], a);
                ldsm4(ql[j], a + AT_QTILE);
            }
        }

        const uint32_t st  = sb + AT_STG(t & 1);
        const uint32_t skh = st + 0 * AT_KTILE;
        const uint32_t svh = st + 2 * AT_KTILE;

        // ---- S = Qhat · K^T (3-way split) ----
#pragma unroll
        for (int nt = 0; nt < 8; nt++) {
#pragma unroll
            for (int j = 0; j < 4; j++) s[nt][j] = 0.0f;
#pragma unroll
            for (int g = 0; g < 2; g++) {
                uint32_t kb[4], klb[4];
                uint32_t a = skh +
                    (uint32_t)((nt * 8 + (lane & 7)) * AT_RSB + g * 64 + (lane >> 3) * 16);
                ldsm4(kb,  a);
                ldsm4(klb, a + AT_KTILE);
                mma_bf16(s[nt], qh[2 * g],     kb);
                mma_bf16(s[nt], qh[2 * g],     klb);
                mma_bf16(s[nt], ql[2 * g],     kb);
                mma_bf16(s[nt], qh[2 * g + 1], kb + 2);
                mma_bf16(s[nt], qh[2 * g + 1], klb + 2);
                mma_bf16(s[nt], ql[2 * g + 1], kb + 2);
            }
        }

        // ---- online softmax (base-2; scale folded into Q) ----
        float tm0 = -1e30f, tm1 = -1e30f;
#pragma unroll
        for (int nt = 0; nt < 8; nt++) {
            tm0 = fmaxf(tm0, fmaxf(s[nt][0], s[nt][1]));
            tm1 = fmaxf(tm1, fmaxf(s[nt][2], s[nt][3]));
        }
        tm0 = fmaxf(tm0, __shfl_xor_sync(0xffffffffu, tm0, 1));
        tm0 = fmaxf(tm0, __shfl_xor_sync(0xffffffffu, tm0, 2));
        tm1 = fmaxf(tm1, __shfl_xor_sync(0xffffffffu, tm1, 1));
        tm1 = fmaxf(tm1, __shfl_xor_sync(0xffffffffu, tm1, 2));

        float mn0 = fmaxf(m0, tm0), mn1 = fmaxf(m1, tm1);
        float cr0 = ex2(m0 - mn0),  cr1 = ex2(m1 - mn1);
        m0 = mn0; m1 = mn1;

        uint32_t ah[4][4], al[4][4];
        float rs0 = 0.0f, rs1 = 0.0f;
#pragma unroll
        for (int nt = 0; nt < 8; nt++) {
            float p0 = ex2(s[nt][0] - mn0);
            float p1 = ex2(s[nt][1] - mn0);
            float p2 = ex2(s[nt][2] - mn1);
            float p3 = ex2(s[nt][3] - mn1);
            rs0 += p0 + p1;
            rs1 += p2 + p3;
            bf16 h0 = __float2bfloat16(p0), h1 = __float2bfloat16(p1);
            bf16 h2 = __float2bfloat16(p2), h3 = __float2bfloat16(p3);
            int kg = nt >> 1, hf = (nt & 1) * 2;
            ah[kg][hf + 0] = packbf(__bfloat162float(h0), __bfloat162float(h1));
            ah[kg][hf + 1] = packbf(__bfloat162float(h2), __bfloat162float(h3));
            al[kg][hf + 0] = packbf(p0 - __bfloat162float(h0), p1 - __bfloat162float(h1));
            al[kg][hf + 1] = packbf(p2 - __bfloat162float(h2), p3 - __bfloat162float(h3));
        }
        rs0 += __shfl_xor_sync(0xffffffffu, rs0, 1);
        rs0 += __shfl_xor_sync(0xffffffffu, rs0, 2);
        rs1 += __shfl_xor_sync(0xffffffffu, rs1, 1);
        rs1 += __shfl_xor_sync(0xffffffffu, rs1, 2);
        l0 = l0 * cr0 + rs0;
        l1 = l1 * cr1 + rs1;
#pragma unroll
        for (int nt = 0; nt < 8; nt++) {
            o[nt][0] *= cr0; o[nt][1] *= cr0;
            o[nt][2] *= cr1; o[nt][3] *= cr1;
        }

        // ---- O += P · V (3-way split), V^T via ldmatrix.trans ----
#pragma unroll
        for (int dp = 0; dp < 4; dp++) {
#pragma unroll
            for (int kg = 0; kg < 4; kg++) {
                uint32_t vb[4], vlb[4];
                uint32_t a = svh +
                    (uint32_t)((kg * 16 + lrow8) * AT_RSB + dp * 32 + lhi16 * 16);
                ldsm4t(vb,  a);
                ldsm4t(vlb, a + AT_KTILE);
                mma_bf16(o[2 * dp],     ah[kg], vb);
                mma_bf16(o[2 * dp],     al[kg], vb);
                mma_bf16(o[2 * dp],     ah[kg], vlb);
                mma_bf16(o[2 * dp + 1], ah[kg], vb + 2);
                mma_bf16(o[2 * dp + 1], al[kg], vb + 2);
                mma_bf16(o[2 * dp + 1], ah[kg], vlb + 2);
            }
        }
        __syncthreads();
    }

    // ---- epilogue: normalize, split hi/lo, store ----
    float inv0 = 1.0f / l0, inv1 = 1.0f / l1;
    int r0 = q0 + wid * 16 + (lane >> 2);
    int cbase = (lane & 3) * 2;
#pragma unroll
    for (int nt = 0; nt < 8; nt++) {
        int col = nt * 8 + cbase;
        float v00 = o[nt][0] * inv0, v01 = o[nt][1] * inv0;
        float v10 = o[nt][2] * inv1, v11 = o[nt][3] * inv1;
        bf16 h00 = __float2bfloat16(v00), h01 = __float2bfloat16(v01);
        bf16 h10 = __float2bfloat16(v10), h11 = __float2bfloat16(v11);
        size_t o0 = base + (size_t)r0 * HIDDEN + col;
        size_t o1 = base + (size_t)(r0 + 8) * HIDDEN + col;
        *(uint32_t*)&g_aoh[o0] = packbf(__bfloat162float(h00), __bfloat162float(h01));
        *(uint32_t*)&g_aoh[o1] = packbf(__bfloat162float(h10), __bfloat162float(h11));
        *(uint32_t*)&g_aol[o0] = packbf(v00 - __bfloat162float(h00), v01 - __bfloat162float(h01));
        *(uint32_t*)&g_aol[o1] = packbf(v10 - __bfloat162float(h10), v11 - __bfloat162float(h11));
    }
}

// ---------------------------------------------------------------------------
extern "C" void kernel_launch(void* const* d_in, const int* in_sizes, int n_in,
                              void* d_out, int out_size)
{
    const float* x  = (const float*)d_in[0];
    const float* Wq = (const float*)d_in[1];
    const float* bq = (const float*)d_in[2];
    const float* Wk = (const float*)d_in[3];
    const float* bk = (const float*)d_in[4];
    const float* Wv = (const float*)d_in[5];
    const float* bv = (const float*)d_in[6];
    const float* Wo = (const float*)d_in[7];
    const float* bo = (const float*)d_in[8];
    float* out = (float*)d_out;

    static int attr_set = 0;
    if (!attr_set) {
        cudaFuncSetAttribute(gemm_qkv_kernel,
                             cudaFuncAttributeMaxDynamicSharedMemorySize, GSMEM);
        cudaFuncSetAttribute(gemm_o_kernel,
                             cudaFuncAttributeMaxDynamicSharedMemorySize, GSMEM);
        cudaFuncSetAttribute(attn_mma_kernel,
                             cudaFuncAttributeMaxDynamicSharedMemorySize, AT_SMEM);
        attr_set = 1;
    }

    split_x_kernel<<<MTOT * HIDDEN / 1024, 256>>>(x);
    wtrans_kernel<<<dim3(32, 32, 4), dim3(32, 8)>>>(Wq, Wk, Wv, Wo);
    gemm_qkv_kernel<<<dim3(HIDDEN / 128, MTOT / 128, 3), 256, GSMEM>>>(bq, bk, bv);
    attn_mma_kernel<<<dim3(SEQ / 128, HEADS, BATCH), 256, AT_SMEM>>>();
    gemm_o_kernel<<<dim3(HIDDEN / 128, MTOT / 128, 1), 256, GSMEM>>>(bo, out);
}

// round 7
// speedup vs baseline: 2.4605x; 1.0119x over previous
#include <cuda_runtime.h>
#include <cuda_bf16.h>
#include <cstdint>

#define HIDDEN 1024
#define SEQ    2048
#define BATCH  2
#define HEADS  16
#define HD     64
#define MTOT   (BATCH*SEQ)   // 4096

typedef __nv_bfloat16 bf16;

// Scale folded into Q projection: 1/sqrt(64) * log2(e)
#define SCALE_Q (0.125f * 1.4426950408889634f)

// ---------------- scratch (device globals) -----------------------------------
__device__ bf16 g_xh [MTOT*HIDDEN];
__device__ bf16 g_xl [MTOT*HIDDEN];
__device__ bf16 g_qh [MTOT*HIDDEN];
__device__ bf16 g_ql [MTOT*HIDDEN];
__device__ bf16 g_kh [MTOT*HIDDEN];
__device__ bf16 g_kl [MTOT*HIDDEN];
__device__ bf16 g_vh [MTOT*HIDDEN];
__device__ bf16 g_vl [MTOT*HIDDEN];
__device__ bf16 g_aoh[MTOT*HIDDEN];
__device__ bf16 g_aol[MTOT*HIDDEN];
__device__ bf16 g_wth[4*HIDDEN*HIDDEN];   // W^T hi, [n][k]
__device__ bf16 g_wtl[4*HIDDEN*HIDDEN];   // W^T lo

// ---------------- helpers ----------------------------------------------------
__device__ __forceinline__ uint32_t smem_u32(const void* p) {
    uint32_t a;
    asm("{ .reg .u64 t; cvta.to.shared.u64 t, %1; cvt.u32.u64 %0, t; }"
        : "=r"(a) : "l"(p));
    return a;
}
__device__ __forceinline__ void cpasync16(uint32_t dst, const void* src) {
    asm volatile("cp.async.cg.shared.global [%0], [%1], 16;"
                 :: "r"(dst), "l"(src));
}
#define CP_COMMIT() asm volatile("cp.async.commit_group;" ::: "memory")
#define CP_WAIT1()  asm volatile("cp.async.wait_group 1;"  ::: "memory")
#define CP_WAIT0()  asm volatile("cp.async.wait_group 0;"  ::: "memory")

__device__ __forceinline__ void mma_bf16(float* c, const uint32_t* a,
                                         const uint32_t* b) {
    asm volatile(
        "mma.sync.aligned.m16n8k16.row.col.f32.bf16.bf16.f32 "
        "{%0,%1,%2,%3}, {%4,%5,%6,%7}, {%8,%9}, {%0,%1,%2,%3};"
        : "+f"(c[0]), "+f"(c[1]), "+f"(c[2]), "+f"(c[3])
        : "r"(a[0]), "r"(a[1]), "r"(a[2]), "r"(a[3]), "r"(b[0]), "r"(b[1]));
}
__device__ __forceinline__ void ldsm4(uint32_t* r, uint32_t addr) {
    asm volatile("ldmatrix.sync.aligned.m8n8.x4.shared.b16 {%0,%1,%2,%3}, [%4];"
                 : "=r"(r[0]), "=r"(r[1]), "=r"(r[2]), "=r"(r[3]) : "r"(addr));
}
__device__ __forceinline__ void ldsm4t(uint32_t* r, uint32_t addr) {
    asm volatile("ldmatrix.sync.aligned.m8n8.x4.trans.shared.b16 {%0,%1,%2,%3}, [%4];"
                 : "=r"(r[0]), "=r"(r[1]), "=r"(r[2]), "=r"(r[3]) : "r"(addr));
}
__device__ __forceinline__ float ex2(float x) {
    float y;
    asm("ex2.approx.ftz.f32 %0, %1;" : "=f"(y) : "f"(x));
    return y;
}
__device__ __forceinline__ uint32_t packbf(float a, float b) {
    __nv_bfloat162 t = __floats2bfloat162_rn(a, b);   // .x = a (low)
    return *(uint32_t*)&t;
}

// ---------------- prep: split fp32 -> bf16 hi/lo -----------------------------
__device__ __forceinline__ void split4(float4 v, ushort4& hv, ushort4& lv) {
    bf16 h0 = __float2bfloat16(v.x), h1 = __float2bfloat16(v.y);
    bf16 h2 = __float2bfloat16(v.z), h3 = __float2bfloat16(v.w);
    hv.x = __bfloat16_as_ushort(h0); hv.y = __bfloat16_as_ushort(h1);
    hv.z = __bfloat16_as_ushort(h2); hv.w = __bfloat16_as_ushort(h3);
    lv.x = __bfloat16_as_ushort(__float2bfloat16(v.x - __bfloat162float(h0)));
    lv.y = __bfloat16_as_ushort(__float2bfloat16(v.y - __bfloat162float(h1)));
    lv.z = __bfloat16_as_ushort(__float2bfloat16(v.z - __bfloat162float(h2)));
    lv.w = __bfloat16_as_ushort(__float2bfloat16(v.w - __bfloat162float(h3)));
}
__global__ __launch_bounds__(256) void split_x_kernel(const float* __restrict__ src) {
    int i = (blockIdx.x * 256 + threadIdx.x) * 4;
    ushort4 hv, lv;
    split4(*(const float4*)&src[i], hv, lv);
    *(ushort4*)&g_xh[i] = hv;
    *(ushort4*)&g_xl[i] = lv;
}

// ---------------- transpose + split weights ----------------------------------
__global__ __launch_bounds__(256) void wtrans_kernel(
    const float* __restrict__ W0, const float* __restrict__ W1,
    const float* __restrict__ W2, const float* __restrict__ W3)
{
    __shared__ float t[32][33];
    const float* W = (blockIdx.z == 0) ? W0 : (blockIdx.z == 1) ? W1
                   : (blockIdx.z == 2) ? W2 : W3;
    bf16* oh = g_wth + (size_t)blockIdx.z * HIDDEN * HIDDEN;
    bf16* ol = g_wtl + (size_t)blockIdx.z * HIDDEN * HIDDEN;
    int n0 = blockIdx.x * 32, k0 = blockIdx.y * 32;
    int tx = threadIdx.x, ty = threadIdx.y;
#pragma unroll
    for (int i = 0; i < 4; i++)
        t[ty + 8 * i][tx] = W[(size_t)(k0 + ty + 8 * i) * HIDDEN + n0 + tx];
    __syncthreads();
#pragma unroll
    for (int i = 0; i < 4; i++) {
        float v = t[tx][ty + 8 * i];
        bf16 h = __float2bfloat16(v);
        bf16 l = __float2bfloat16(v - __bfloat162float(h));
        size_t o = (size_t)(n0 + ty + 8 * i) * HIDDEN + k0 + tx;
        oh[o] = h;
        ol[o] = l;
    }
}

// ---------------- bf16x3 GEMM via mma.sync + ldmatrix ------------------------
#define KCH    32
#define NCHK   (HIDDEN / KCH)   // 32
#define ARR_B  (128 * 80)            // 10240 bytes per array (80B row stride)
#define STG_B  (4 * ARR_B)           // 40960 bytes
#define GSMEM  (2 * STG_B)           // 81920 bytes

__device__ __forceinline__ void g_load_stage(
    uint32_t sbase, const bf16* __restrict__ Ah, const bf16* __restrict__ Al,
    const bf16* __restrict__ Bh, const bf16* __restrict__ Bl, int ko, int tid)
{
#pragma unroll
    for (int l = 0; l < 2; l++) {
        int fi  = tid + 256 * l;
        int row = fi >> 2;
        int w   = fi & 3;
        uint32_t so = sbase + (uint32_t)(row * 80 + w * 16);
        size_t   go = (size_t)row * HIDDEN + ko + w * 8;
        cpasync16(so + 0 * ARR_B, Ah + go);
        cpasync16(so + 1 * ARR_B, Al + go);
        cpasync16(so + 2 * ARR_B, Bh + go);
        cpasync16(so + 3 * ARR_B, Bl + go);
    }
}

// ldmatrix-based compute: per warp 24 ldsm.x4 + 96 HMMA per chunk.
__device__ __forceinline__ void g_compute_ldsm(
    uint32_t sb, int m_w, int n_w, int lane, float acc[4][4][4])
{
    const int lrow8 = (lane & 7) + ((lane >> 3) & 1) * 8;
    const int lhi16 = lane >> 4;
    const int bcol  = (lane >> 3) * 16;

    // B fragments: per ni, n8 x k32 (both k16 halves) — validated K pattern.
    uint32_t Bh[4][4], Bl[4][4];
#pragma unroll
    for (int ni = 0; ni < 4; ni++) {
        uint32_t a = sb + 2 * ARR_B +
                     (uint32_t)((n_w + ni * 8 + (lane & 7)) * 80 + bcol);
        ldsm4(Bh[ni], a);
        ldsm4(Bl[ni], a + ARR_B);
    }

#pragma unroll
    for (int ks = 0; ks < 2; ks++) {
#pragma unroll
        for (int mi = 0; mi < 4; mi++) {
            // A fragment m16 x k16 — validated Q pattern.
            uint32_t a = sb +
                (uint32_t)((m_w + mi * 16 + lrow8) * 80 + ks * 32 + lhi16 * 16);
            uint32_t ah[4], al[4];
            ldsm4(ah, a);
            ldsm4(al, a + ARR_B);
#pragma unroll
            for (int ni = 0; ni < 4; ni++) {
                mma_bf16(acc[mi][ni], ah, Bh[ni] + 2 * ks);
                mma_bf16(acc[mi][ni], ah, Bl[ni] + 2 * ks);
                mma_bf16(acc[mi][ni], al, Bh[ni] + 2 * ks);
            }
        }
    }
}

// Fused compute core; epilogue selected by Cf (fp32) vs Ch/Cl (split bf16).
__device__ __forceinline__ void gemm_body_mma(
    const bf16* __restrict__ Ah0, const bf16* __restrict__ Al0,
    const bf16* __restrict__ Bh0, const bf16* __restrict__ Bl0,
    const float* __restrict__ bias,
    float* __restrict__ Cf, bf16* __restrict__ Ch, bf16* __restrict__ Cl,
    float scale, int m0, int n0)
{
    extern __shared__ char sm[];
    const int tid  = threadIdx.x;
    const int wid  = tid >> 5;
    const int lane = tid & 31;
    const int lr = lane >> 2, lc = lane & 3;
    const int m_w = (wid & 1) * 64;
    const int n_w = (wid >> 1) * 32;

    const bf16* Ah = Ah0 + (size_t)m0 * HIDDEN;
    const bf16* Al = Al0 + (size_t)m0 * HIDDEN;
    const bf16* Bh = Bh0 + (size_t)n0 * HIDDEN;
    const bf16* Bl = Bl0 + (size_t)n0 * HIDDEN;

    float acc[4][4][4];
#pragma unroll
    for (int i = 0; i < 4; i++)
#pragma unroll
        for (int j = 0; j < 4; j++)
#pragma unroll
            for (int k = 0; k < 4; k++) acc[i][j][k] = 0.0f;

    const uint32_t sb = smem_u32(sm);
    g_load_stage(sb, Ah, Al, Bh, Bl, 0, tid);
    CP_COMMIT();

    // Single-sync pipeline: wait -> barrier -> issue next load -> compute.
    for (int c = 0; c < NCHK; c++) {
        CP_WAIT0();
        __syncthreads();
        if (c + 1 < NCHK) {
            g_load_stage(sb + ((c + 1) & 1) * STG_B, Ah, Al, Bh, Bl,
                         (c + 1) * KCH, tid);
            CP_COMMIT();
        }
        g_compute_ldsm(sb + (c & 1) * STG_B, m_w, n_w, lane, acc);
    }

#pragma unroll
    for (int mi = 0; mi < 4; mi++) {
#pragma unroll
        for (int ni = 0; ni < 4; ni++) {
            int row = m0 + m_w + mi * 16 + lr;
            int col = n0 + n_w + ni * 8 + lc * 2;
            float b0 = bias[col], b1 = bias[col + 1];
            float v00 = (acc[mi][ni][0] + b0) * scale;
            float v01 = (acc[mi][ni][1] + b1) * scale;
            float v10 = (acc[mi][ni][2] + b0) * scale;
            float v11 = (acc[mi][ni][3] + b1) * scale;
            if (Cf) {
                *(float2*)&Cf[(size_t)row * HIDDEN + col]       = make_float2(v00, v01);
                *(float2*)&Cf[(size_t)(row + 8) * HIDDEN + col] = make_float2(v10, v11);
            } else {
                bf16 h00 = __float2bfloat16(v00), h01 = __float2bfloat16(v01);
                bf16 h10 = __float2bfloat16(v10), h11 = __float2bfloat16(v11);
                *(uint32_t*)&Ch[(size_t)row * HIDDEN + col] =
                    packbf(__bfloat162float(h00), __bfloat162float(h01));
                *(uint32_t*)&Ch[(size_t)(row + 8) * HIDDEN + col] =
                    packbf(__bfloat162float(h10), __bfloat162float(h11));
                *(uint32_t*)&Cl[(size_t)row * HIDDEN + col] =
                    packbf(v00 - __bfloat162float(h00), v01 - __bfloat162float(h01));
                *(uint32_t*)&Cl[(size_t)(row + 8) * HIDDEN + col] =
                    packbf(v10 - __bfloat162float(h10), v11 - __bfloat162float(h11));
            }
        }
    }
}

__global__ __launch_bounds__(256, 2) void gemm_qkv_kernel(
    const float* __restrict__ bq, const float* __restrict__ bk,
    const float* __restrict__ bv)
{
    const bf16* Bh; const bf16* Bl; const float* bias;
    bf16 *Ch, *Cl; float scale;
    if (blockIdx.z == 0) {
        Bh = g_wth; Bl = g_wtl; bias = bq; Ch = g_qh; Cl = g_ql; scale = SCALE_Q;
    } else if (blockIdx.z == 1) {
        Bh = g_wth + 1 * HIDDEN * HIDDEN; Bl = g_wtl + 1 * HIDDEN * HIDDEN;
        bias = bk; Ch = g_kh; Cl = g_kl; scale = 1.0f;
    } else {
        Bh = g_wth + 2 * HIDDEN * HIDDEN; Bl = g_wtl + 2 * HIDDEN * HIDDEN;
        bias = bv; Ch = g_vh; Cl = g_vl; scale = 1.0f;
    }
    gemm_body_mma(g_xh, g_xl, Bh, Bl, bias, nullptr, Ch, Cl, scale,
                  blockIdx.y * 128, blockIdx.x * 128);
}

__global__ __launch_bounds__(256, 2) void gemm_o_kernel(
    const float* __restrict__ bo, float* __restrict__ out)
{
    gemm_body_mma(g_aoh, g_aol,
                  g_wth + 3 * HIDDEN * HIDDEN, g_wtl + 3 * HIDDEN * HIDDEN,
                  bo, out, nullptr, nullptr, 1.0f,
                  blockIdx.y * 128, blockIdx.x * 128);
}

// ---------------- flash attention on mma.sync (bf16 hi/lo) -------------------
// CTA: 256 threads (8 warps), q-tile 128, key tiles of 64.
// 3-stage KV pipeline (prefetch distance 2), ONE __syncthreads per tile.
// Q staged through stage 2's SMEM, then register-resident.
// SMEM: 3 stages x {Kh,Kl,Vh,Vl}[64][72] = 110592 B -> 2 CTAs/SM.
#define AT_RSB   144
#define AT_KTILE (64 * AT_RSB)                  // 9216
#define AT_STG(s) ((s) * 4 * AT_KTILE)          // 36864 per stage
#define AT_SMEM  (12 * AT_KTILE)                // 110592
#define NKT      (SEQ / 64)                     // 32

__device__ __forceinline__ void at_load_kv(uint32_t sdst, size_t gbase,
                                           int kt, int tid)
{
    int row = tid >> 2;               // 0..63
    int c0  = (tid & 3) * 32;         // 0,32,64,96 bytes
    size_t go = gbase + (size_t)(kt + row) * HIDDEN;
    const char* kh = (const char*)(g_kh + go);
    const char* kl = (const char*)(g_kl + go);
    const char* vh = (const char*)(g_vh + go);
    const char* vl = (const char*)(g_vl + go);
    uint32_t sd = sdst + (uint32_t)(row * AT_RSB + c0);
#pragma unroll
    for (int i = 0; i < 2; i++) {
        cpasync16(sd + 0 * AT_KTILE + i * 16, kh + c0 + i * 16);
        cpasync16(sd + 1 * AT_KTILE + i * 16, kl + c0 + i * 16);
        cpasync16(sd + 2 * AT_KTILE + i * 16, vh + c0 + i * 16);
        cpasync16(sd + 3 * AT_KTILE + i * 16, vl + c0 + i * 16);
    }
}

__global__ __launch_bounds__(256, 2) void attn_mma_kernel()
{
    extern __shared__ char sma[];
    const int tid  = threadIdx.x;
    const int wid  = tid >> 5;
    const int lane = tid & 31;
    const int q0 = blockIdx.x * 128;
    const int h  = blockIdx.y;
    const int b  = blockIdx.z;
    const size_t base = (size_t)b * SEQ * HIDDEN + (size_t)h * HD;
    const uint32_t sb = smem_u32(sma);

    // Q (hi+lo) into stage-2 area: Qh at +0, Ql at +2*AT_KTILE (18432).
    {
        int row = tid >> 1;
        int c0  = (tid & 1) * 64;
        size_t go = base + (size_t)(q0 + row) * HIDDEN;
        const char* qh = (const char*)(g_qh + go);
        const char* ql = (const char*)(g_ql + go);
        uint32_t sd = sb + AT_STG(2) + (uint32_t)(row * AT_RSB + c0);
#pragma unroll
        for (int i = 0; i < 4; i++) {
            cpasync16(sd + i * 16,                  qh + c0 + i * 16);
            cpasync16(sd + 2 * AT_KTILE + i * 16,   ql + c0 + i * 16);
        }
    }
    CP_COMMIT();                                     // g0: Q
    at_load_kv(sb + AT_STG(0), base, 0, tid);
    CP_COMMIT();                                     // g1: KV0
    at_load_kv(sb + AT_STG(1), base, 64, tid);
    CP_COMMIT();                                     // g2: KV1

    uint32_t qh[4][4], ql[4][4];
    float    s[8][4], o[8][4];
    float m0 = -1e30f, m1 = -1e30f, l0 = 0.0f, l1 = 0.0f;
#pragma unroll
    for (int i = 0; i < 8; i++)
#pragma unroll
        for (int j = 0; j < 4; j++) o[i][j] = 0.0f;

    const int lrow8 = (lane & 7) + ((lane >> 3) & 1) * 8;
    const int lhi16 = (lane >> 4);

    int sidx = 0;                                    // t % 3
    for (int t = 0; t < NKT; t++) {
        if (t + 1 < NKT) { CP_WAIT1(); } else { CP_WAIT0(); }
        __syncthreads();

        if (t == 0) {
            // Q fragments from stage 2, then barrier before stage 2 is recycled.
#pragma unroll
            for (int j = 0; j < 4; j++) {
                uint32_t a = sb + AT_STG(2) +
                    (uint32_t)((wid * 16 + lrow8) * AT_RSB + j * 32 + lhi16 * 16);
                ldsm4(qh[j], a);
                ldsm4(ql[j], a + 2 * AT_KTILE);
            }
            __syncthreads();
        }

        if (t + 2 < NKT) {
            int ps = sidx + 2; if (ps >= 3) ps -= 3;
            at_load_kv(sb + AT_STG(ps), base, (t + 2) * 64, tid);
            CP_COMMIT();
        }

        const uint32_t st  = sb + AT_STG(sidx);
        const uint32_t skh = st + 0 * AT_KTILE;
        const uint32_t svh = st + 2 * AT_KTILE;

        // ---- S = Qhat · K^T (3-way split) ----
#pragma unroll
        for (int nt = 0; nt < 8; nt++) {
#pragma unroll
            for (int j = 0; j < 4; j++) s[nt][j] = 0.0f;
#pragma unroll
            for (int g = 0; g < 2; g++) {
                uint32_t kb[4], klb[4];
                uint32_t a = skh +
                    (uint32_t)((nt * 8 + (lane & 7)) * AT_RSB + g * 64 + (lane >> 3) * 16);
                ldsm4(kb,  a);
                ldsm4(klb, a + AT_KTILE);
                mma_bf16(s[nt], qh[2 * g],     kb);
                mma_bf16(s[nt], qh[2 * g],     klb);
                mma_bf16(s[nt], ql[2 * g],     kb);
                mma_bf16(s[nt], qh[2 * g + 1], kb + 2);
                mma_bf16(s[nt], qh[2 * g + 1], klb + 2);
                mma_bf16(s[nt], ql[2 * g + 1], kb + 2);
            }
        }

        // ---- online softmax (base-2; scale folded into Q) ----
        float tm0 = -1e30f, tm1 = -1e30f;
#pragma unroll
        for (int nt = 0; nt < 8; nt++) {
            tm0 = fmaxf(tm0, fmaxf(s[nt][0], s[nt][1]));
            tm1 = fmaxf(tm1, fmaxf(s[nt][2], s[nt][3]));
        }
        tm0 = fmaxf(tm0, __shfl_xor_sync(0xffffffffu, tm0, 1));
        tm0 = fmaxf(tm0, __shfl_xor_sync(0xffffffffu, tm0, 2));
        tm1 = fmaxf(tm1, __shfl_xor_sync(0xffffffffu, tm1, 1));
        tm1 = fmaxf(tm1, __shfl_xor_sync(0xffffffffu, tm1, 2));

        float mn0 = fmaxf(m0, tm0), mn1 = fmaxf(m1, tm1);
        float cr0 = ex2(m0 - mn0),  cr1 = ex2(m1 - mn1);
        m0 = mn0; m1 = mn1;

        uint32_t ah[4][4], al[4][4];
        float rs0 = 0.0f, rs1 = 0.0f;
#pragma unroll
        for (int nt = 0; nt < 8; nt++) {
            float p0 = ex2(s[nt][0] - mn0);
            float p1 = ex2(s[nt][1] - mn0);
            float p2 = ex2(s[nt][2] - mn1);
            float p3 = ex2(s[nt][3] - mn1);
            rs0 += p0 + p1;
            rs1 += p2 + p3;
            bf16 h0 = __float2bfloat16(p0), h1 = __float2bfloat16(p1);
            bf16 h2 = __float2bfloat16(p2), h3 = __float2bfloat16(p3);
            int kg = nt >> 1, hf = (nt & 1) * 2;
            ah[kg][hf + 0] = packbf(__bfloat162float(h0), __bfloat162float(h1));
            ah[kg][hf + 1] = packbf(__bfloat162float(h2), __bfloat162float(h3));
            al[kg][hf + 0] = packbf(p0 - __bfloat162float(h0), p1 - __bfloat162float(h1));
            al[kg][hf + 1] = packbf(p2 - __bfloat162float(h2), p3 - __bfloat162float(h3));
        }
        rs0 += __shfl_xor_sync(0xffffffffu, rs0, 1);
        rs0 += __shfl_xor_sync(0xffffffffu, rs0, 2);
        rs1 += __shfl_xor_sync(0xffffffffu, rs1, 1);
        rs1 += __shfl_xor_sync(0xffffffffu, rs1, 2);
        l0 = l0 * cr0 + rs0;
        l1 = l1 * cr1 + rs1;
#pragma unroll
        for (int nt = 0; nt < 8; nt++) {
            o[nt][0] *= cr0; o[nt][1] *= cr0;
            o[nt][2] *= cr1; o[nt][3] *= cr1;
        }

        // ---- O += P · V (3-way split), V^T via ldmatrix.trans ----
#pragma unroll
        for (int dp = 0; dp < 4; dp++) {
#pragma unroll
            for (int kg = 0; kg < 4; kg++) {
                uint32_t vb[4], vlb[4];
                uint32_t a = svh +
                    (uint32_t)((kg * 16 + lrow8) * AT_RSB + dp * 32 + lhi16 * 16);
                ldsm4t(vb,  a);
                ldsm4t(vlb, a + AT_KTILE);
                mma_bf16(o[2 * dp],     ah[kg], vb);
                mma_bf16(o[2 * dp],     al[kg], vb);
                mma_bf16(o[2 * dp],     ah[kg], vlb);
                mma_bf16(o[2 * dp + 1], ah[kg], vb + 2);
                mma_bf16(o[2 * dp + 1], al[kg], vb + 2);
                mma_bf16(o[2 * dp + 1], ah[kg], vlb + 2);
            }
        }

        if (++sidx == 3) sidx = 0;
    }

    // ---- epilogue: normalize, split hi/lo, store ----
    float inv0 = 1.0f / l0, inv1 = 1.0f / l1;
    int r0 = q0 + wid * 16 + (lane >> 2);
    int cbase = (lane & 3) * 2;
#pragma unroll
    for (int nt = 0; nt < 8; nt++) {
        int col = nt * 8 + cbase;
        float v00 = o[nt][0] * inv0, v01 = o[nt][1] * inv0;
        float v10 = o[nt][2] * inv1, v11 = o[nt][3] * inv1;
        bf16 h00 = __float2bfloat16(v00), h01 = __float2bfloat16(v01);
        bf16 h10 = __float2bfloat16(v10), h11 = __float2bfloat16(v11);
        size_t o0 = base + (size_t)r0 * HIDDEN + col;
        size_t o1 = base + (size_t)(r0 + 8) * HIDDEN + col;
        *(uint32_t*)&g_aoh[o0] = packbf(__bfloat162float(h00), __bfloat162float(h01));
        *(uint32_t*)&g_aoh[o1] = packbf(__bfloat162float(h10), __bfloat162float(h11));
        *(uint32_t*)&g_aol[o0] = packbf(v00 - __bfloat162float(h00), v01 - __bfloat162float(h01));
        *(uint32_t*)&g_aol[o1] = packbf(v10 - __bfloat162float(h10), v11 - __bfloat162float(h11));
    }
}

// ---------------------------------------------------------------------------
extern "C" void kernel_launch(void* const* d_in, const int* in_sizes, int n_in,
                              void* d_out, int out_size)
{
    const float* x  = (const float*)d_in[0];
    const float* Wq = (const float*)d_in[1];
    const float* bq = (const float*)d_in[2];
    const float* Wk = (const float*)d_in[3];
    const float* bk = (const float*)d_in[4];
    const float* Wv = (const float*)d_in[5];
    const float* bv = (const float*)d_in[6];
    const float* Wo = (const float*)d_in[7];
    const float* bo = (const float*)d_in[8];
    float* out = (float*)d_out;

    static int attr_set = 0;
    if (!attr_set) {
        cudaFuncSetAttribute(gemm_qkv_kernel,
                             cudaFuncAttributeMaxDynamicSharedMemorySize, GSMEM);
        cudaFuncSetAttribute(gemm_o_kernel,
                             cudaFuncAttributeMaxDynamicSharedMemorySize, GSMEM);
        cudaFuncSetAttribute(attn_mma_kernel,
                             cudaFuncAttributeMaxDynamicSharedMemorySize, AT_SMEM);
        attr_set = 1;
    }

    split_x_kernel<<<MTOT * HIDDEN / 1024, 256>>>(x);
    wtrans_kernel<<<dim3(32, 32, 4), dim3(32, 8)>>>(Wq, Wk, Wv, Wo);
    gemm_qkv_kernel<<<dim3(HIDDEN / 128, MTOT / 128, 3), 256, GSMEM>>>(bq, bk, bv);
    attn_mma_kernel<<<dim3(SEQ / 128, HEADS, BATCH), 256, AT_SMEM>>>();
    gemm_o_kernel<<<dim3(HIDDEN / 128, MTOT / 128, 1), 256, GSMEM>>>(bo, out);
}

// round 8
// speedup vs baseline: 3.3899x; 1.3777x over previous
#include <cuda_runtime.h>
#include <cuda_fp16.h>
#include <cstdint>

#define HIDDEN 1024
#define SEQ    2048
#define BATCH  2
#define HEADS  16
#define HD     64
#define MTOT   (BATCH*SEQ)   // 4096

typedef __half fp16;

// Scale folded into Q projection: 1/sqrt(64) * log2(e)
#define SCALE_Q (0.125f * 1.4426950408889634f)

// ---------------- scratch (device globals) -----------------------------------
__device__ fp16 g_x  [MTOT*HIDDEN];       // x, fp16 (A of QKV gemms)
__device__ fp16 g_q  [MTOT*HIDDEN];       // Q, fp16, pre-scaled
__device__ fp16 g_kh [MTOT*HIDDEN];
__device__ fp16 g_kl [MTOT*HIDDEN];
__device__ fp16 g_vh [MTOT*HIDDEN];
__device__ fp16 g_vl [MTOT*HIDDEN];
__device__ fp16 g_ao [MTOT*HIDDEN];       // attn out, fp16 (A of O gemm)
__device__ fp16 g_wh [4*HIDDEN*HIDDEN];   // W^T hi, [n][k]
__device__ fp16 g_wl [4*HIDDEN*HIDDEN];   // W^T lo

// ---------------- helpers ----------------------------------------------------
__device__ __forceinline__ uint32_t smem_u32(const void* p) {
    uint32_t a;
    asm("{ .reg .u64 t; cvta.to.shared.u64 t, %1; cvt.u32.u64 %0, t; }"
        : "=r"(a) : "l"(p));
    return a;
}
__device__ __forceinline__ void cpasync16(uint32_t dst, const void* src) {
    asm volatile("cp.async.cg.shared.global [%0], [%1], 16;"
                 :: "r"(dst), "l"(src));
}
#define CP_COMMIT() asm volatile("cp.async.commit_group;" ::: "memory")
#define CP_WAIT1()  asm volatile("cp.async.wait_group 1;"  ::: "memory")
#define CP_WAIT0()  asm volatile("cp.async.wait_group 0;"  ::: "memory")

__device__ __forceinline__ void mma_fp16(float* c, const uint32_t* a,
                                         const uint32_t* b) {
    asm volatile(
        "mma.sync.aligned.m16n8k16.row.col.f32.f16.f16.f32 "
        "{%0,%1,%2,%3}, {%4,%5,%6,%7}, {%8,%9}, {%0,%1,%2,%3};"
        : "+f"(c[0]), "+f"(c[1]), "+f"(c[2]), "+f"(c[3])
        : "r"(a[0]), "r"(a[1]), "r"(a[2]), "r"(a[3]), "r"(b[0]), "r"(b[1]));
}
__device__ __forceinline__ void ldsm4(uint32_t* r, uint32_t addr) {
    asm volatile("ldmatrix.sync.aligned.m8n8.x4.shared.b16 {%0,%1,%2,%3}, [%4];"
                 : "=r"(r[0]), "=r"(r[1]), "=r"(r[2]), "=r"(r[3]) : "r"(addr));
}
__device__ __forceinline__ void ldsm4t(uint32_t* r, uint32_t addr) {
    asm volatile("ldmatrix.sync.aligned.m8n8.x4.trans.shared.b16 {%0,%1,%2,%3}, [%4];"
                 : "=r"(r[0]), "=r"(r[1]), "=r"(r[2]), "=r"(r[3]) : "r"(addr));
}
__device__ __forceinline__ float ex2(float x) {
    float y;
    asm("ex2.approx.ftz.f32 %0, %1;" : "=f"(y) : "f"(x));
    return y;
}
__device__ __forceinline__ uint32_t packh2(float a, float b) {
    __half2 t = __floats2half2_rn(a, b);   // .x = a (low half)
    return *(uint32_t*)&t;
}

// ---------------- prep: x -> fp16 --------------------------------------------
__global__ __launch_bounds__(256) void split_x_kernel(const float* __restrict__ src) {
    int i = (blockIdx.x * 256 + threadIdx.x) * 4;
    float4 v = *(const float4*)&src[i];
    uint2 o;
    o.x = packh2(v.x, v.y);
    o.y = packh2(v.z, v.w);
    *(uint2*)&g_x[i] = o;
}

// ---------------- transpose + split weights: W[K][N] -> Wt[N][K] hi/lo fp16 --
__global__ __launch_bounds__(256) void wtrans_kernel(
    const float* __restrict__ W0, const float* __restrict__ W1,
    const float* __restrict__ W2, const float* __restrict__ W3)
{
    __shared__ float t[32][33];
    const float* W = (blockIdx.z == 0) ? W0 : (blockIdx.z == 1) ? W1
                   : (blockIdx.z == 2) ? W2 : W3;
    fp16* oh = g_wh + (size_t)blockIdx.z * HIDDEN * HIDDEN;
    fp16* ol = g_wl + (size_t)blockIdx.z * HIDDEN * HIDDEN;
    int n0 = blockIdx.x * 32, k0 = blockIdx.y * 32;
    int tx = threadIdx.x, ty = threadIdx.y;
#pragma unroll
    for (int i = 0; i < 4; i++)
        t[ty + 8 * i][tx] = W[(size_t)(k0 + ty + 8 * i) * HIDDEN + n0 + tx];
    __syncthreads();
#pragma unroll
    for (int i = 0; i < 4; i++) {
        float v = t[tx][ty + 8 * i];
        fp16 h = __float2half_rn(v);
        fp16 l = __float2half_rn(v - __half2float(h));
        size_t o = (size_t)(n0 + ty + 8 * i) * HIDDEN + k0 + tx;
        oh[o] = h;
        ol[o] = l;
    }
}

// ---------------- fp16 2-term GEMM via mma.sync + ldmatrix -------------------
// C = A(fp16) @ (Wh + Wl) + bias. CTA 128x128, K-chunk 32, 256 threads.
// SMEM/stage: A (10240) + Bh (10240) + Bl (10240); 80B row stride.
#define KCH    32
#define NCHK   (HIDDEN / KCH)   // 32
#define ARR_B  (128 * 80)            // 10240 bytes per array
#define STG_B  (3 * ARR_B)           // 30720 bytes
#define GSMEM  (2 * STG_B)           // 61440 bytes

__device__ __forceinline__ void g_load_stage(
    uint32_t sbase, const fp16* __restrict__ A,
    const fp16* __restrict__ Bh, const fp16* __restrict__ Bl, int ko, int tid)
{
#pragma unroll
    for (int l = 0; l < 2; l++) {
        int fi  = tid + 256 * l;
        int row = fi >> 2;
        int w   = fi & 3;
        uint32_t so = sbase + (uint32_t)(row * 80 + w * 16);
        size_t   go = (size_t)row * HIDDEN + ko + w * 8;
        cpasync16(so + 0 * ARR_B, A  + go);
        cpasync16(so + 1 * ARR_B, Bh + go);
        cpasync16(so + 2 * ARR_B, Bl + go);
    }
}

// Per warp per chunk: 8 A-ldsm + 8 B-ldsm + 64 HMMA.
__device__ __forceinline__ void g_compute_ldsm(
    uint32_t sb, int m_w, int n_w, int lane, float acc[4][4][4])
{
    const int lrow8 = (lane & 7) + ((lane >> 3) & 1) * 8;
    const int lhi16 = lane >> 4;
    const int bcol  = (lane >> 3) * 16;

    uint32_t Bh[4][4], Bl[4][4];
#pragma unroll
    for (int ni = 0; ni < 4; ni++) {
        uint32_t a = sb + 1 * ARR_B +
                     (uint32_t)((n_w + ni * 8 + (lane & 7)) * 80 + bcol);
        ldsm4(Bh[ni], a);
        ldsm4(Bl[ni], a + ARR_B);
    }

#pragma unroll
    for (int ks = 0; ks < 2; ks++) {
#pragma unroll
        for (int mi = 0; mi < 4; mi++) {
            uint32_t a = sb +
                (uint32_t)((m_w + mi * 16 + lrow8) * 80 + ks * 32 + lhi16 * 16);
            uint32_t ar[4];
            ldsm4(ar, a);
#pragma unroll
            for (int ni = 0; ni < 4; ni++) {
                mma_fp16(acc[mi][ni], ar, Bh[ni] + 2 * ks);
                mma_fp16(acc[mi][ni], ar, Bl[ni] + 2 * ks);
            }
        }
    }
}

// Epilogue modes: Cf != 0 -> fp32; else Cl != 0 -> fp16 hi/lo; else fp16 single.
__device__ __forceinline__ void gemm_body_mma(
    const fp16* __restrict__ A0,
    const fp16* __restrict__ Bh0, const fp16* __restrict__ Bl0,
    const float* __restrict__ bias,
    float* __restrict__ Cf, fp16* __restrict__ Ch, fp16* __restrict__ Cl,
    float scale, int m0, int n0)
{
    extern __shared__ char sm[];
    const int tid  = threadIdx.x;
    const int wid  = tid >> 5;
    const int lane = tid & 31;
    const int lr = lane >> 2, lc = lane & 3;
    const int m_w = (wid & 1) * 64;
    const int n_w = (wid >> 1) * 32;

    const fp16* A  = A0  + (size_t)m0 * HIDDEN;
    const fp16* Bh = Bh0 + (size_t)n0 * HIDDEN;
    const fp16* Bl = Bl0 + (size_t)n0 * HIDDEN;

    float acc[4][4][4];
#pragma unroll
    for (int i = 0; i < 4; i++)
#pragma unroll
        for (int j = 0; j < 4; j++)
#pragma unroll
            for (int k = 0; k < 4; k++) acc[i][j][k] = 0.0f;

    const uint32_t sb = smem_u32(sm);
    g_load_stage(sb, A, Bh, Bl, 0, tid);
    CP_COMMIT();

    for (int c = 0; c < NCHK; c++) {
        CP_WAIT0();
        __syncthreads();
        if (c + 1 < NCHK) {
            g_load_stage(sb + ((c + 1) & 1) * STG_B, A, Bh, Bl,
                         (c + 1) * KCH, tid);
            CP_COMMIT();
        }
        g_compute_ldsm(sb + (c & 1) * STG_B, m_w, n_w, lane, acc);
    }

#pragma unroll
    for (int mi = 0; mi < 4; mi++) {
#pragma unroll
        for (int ni = 0; ni < 4; ni++) {
            int row = m0 + m_w + mi * 16 + lr;
            int col = n0 + n_w + ni * 8 + lc * 2;
            float b0 = bias[col], b1 = bias[col + 1];
            float v00 = (acc[mi][ni][0] + b0) * scale;
            float v01 = (acc[mi][ni][1] + b1) * scale;
            float v10 = (acc[mi][ni][2] + b0) * scale;
            float v11 = (acc[mi][ni][3] + b1) * scale;
            if (Cf) {
                *(float2*)&Cf[(size_t)row * HIDDEN + col]       = make_float2(v00, v01);
                *(float2*)&Cf[(size_t)(row + 8) * HIDDEN + col] = make_float2(v10, v11);
            } else if (Cl) {
                fp16 h00 = __float2half_rn(v00), h01 = __float2half_rn(v01);
                fp16 h10 = __float2half_rn(v10), h11 = __float2half_rn(v11);
                *(uint32_t*)&Ch[(size_t)row * HIDDEN + col] =
                    packh2(__half2float(h00), __half2float(h01));
                *(uint32_t*)&Ch[(size_t)(row + 8) * HIDDEN + col] =
                    packh2(__half2float(h10), __half2float(h11));
                *(uint32_t*)&Cl[(size_t)row * HIDDEN + col] =
                    packh2(v00 - __half2float(h00), v01 - __half2float(h01));
                *(uint32_t*)&Cl[(size_t)(row + 8) * HIDDEN + col] =
                    packh2(v10 - __half2float(h10), v11 - __half2float(h11));
            } else {
                *(uint32_t*)&Ch[(size_t)row * HIDDEN + col]       = packh2(v00, v01);
                *(uint32_t*)&Ch[(size_t)(row + 8) * HIDDEN + col] = packh2(v10, v11);
            }
        }
    }
}

__global__ __launch_bounds__(256, 2) void gemm_qkv_kernel(
    const float* __restrict__ bq, const float* __restrict__ bk,
    const float* __restrict__ bv)
{
    const fp16* Bh; const fp16* Bl; const float* bias;
    fp16 *Ch, *Cl; float scale;
    if (blockIdx.z == 0) {
        Bh = g_wh; Bl = g_wl; bias = bq;
        Ch = g_q; Cl = nullptr; scale = SCALE_Q;            // Q: fp16 single
    } else if (blockIdx.z == 1) {
        Bh = g_wh + 1 * HIDDEN * HIDDEN; Bl = g_wl + 1 * HIDDEN * HIDDEN;
        bias = bk; Ch = g_kh; Cl = g_kl; scale = 1.0f;      // K: hi/lo
    } else {
        Bh = g_wh + 2 * HIDDEN * HIDDEN; Bl = g_wl + 2 * HIDDEN * HIDDEN;
        bias = bv; Ch = g_vh; Cl = g_vl; scale = 1.0f;      // V: hi/lo
    }
    gemm_body_mma(g_x, Bh, Bl, bias, nullptr, Ch, Cl, scale,
                  blockIdx.y * 128, blockIdx.x * 128);
}

__global__ __launch_bounds__(256, 2) void gemm_o_kernel(
    const float* __restrict__ bo, float* __restrict__ out)
{
    gemm_body_mma(g_ao,
                  g_wh + 3 * HIDDEN * HIDDEN, g_wl + 3 * HIDDEN * HIDDEN,
                  bo, out, nullptr, nullptr, 1.0f,
                  blockIdx.y * 128, blockIdx.x * 128);
}

// ---------------- flash attention, fp16 2-term -------------------------------
// CTA: 256 threads (8 warps), q-tile 128, key tiles of 64, 3-stage KV pipeline.
// Q fp16 single; K,V hi/lo. S = Q·Kh + Q·Kl ; O += P·Vh + P·Vl (P fp16).
#define AT_RSB   144
#define AT_KTILE (64 * AT_RSB)                  // 9216
#define AT_STG(s) ((s) * 4 * AT_KTILE)          // 36864 per stage
#define AT_SMEM  (12 * AT_KTILE)                // 110592 -> 2 CTAs/SM
#define NKT      (SEQ / 64)                     // 32

__device__ __forceinline__ void at_load_kv(uint32_t sdst, size_t gbase,
                                           int kt, int tid)
{
    int row = tid >> 2;               // 0..63
    int c0  = (tid & 3) * 32;         // 0,32,64,96 bytes
    size_t go = gbase + (size_t)(kt + row) * HIDDEN;
    const char* kh = (const char*)(g_kh + go);
    const char* kl = (const char*)(g_kl + go);
    const char* vh = (const char*)(g_vh + go);
    const char* vl = (const char*)(g_vl + go);
    uint32_t sd = sdst + (uint32_t)(row * AT_RSB + c0);
#pragma unroll
    for (int i = 0; i < 2; i++) {
        cpasync16(sd + 0 * AT_KTILE + i * 16, kh + c0 + i * 16);
        cpasync16(sd + 1 * AT_KTILE + i * 16, kl + c0 + i * 16);
        cpasync16(sd + 2 * AT_KTILE + i * 16, vh + c0 + i * 16);
        cpasync16(sd + 3 * AT_KTILE + i * 16, vl + c0 + i * 16);
    }
}

__global__ __launch_bounds__(256, 2) void attn_mma_kernel()
{
    extern __shared__ char sma[];
    const int tid  = threadIdx.x;
    const int wid  = tid >> 5;
    const int lane = tid & 31;
    const int q0 = blockIdx.x * 128;
    const int h  = blockIdx.y;
    const int b  = blockIdx.z;
    const size_t base = (size_t)b * SEQ * HIDDEN + (size_t)h * HD;
    const uint32_t sb = smem_u32(sma);

    // Q (fp16 single) into stage-2 area.
    {
        int row = tid >> 1;
        int c0  = (tid & 1) * 64;
        size_t go = base + (size_t)(q0 + row) * HIDDEN;
        const char* qp = (const char*)(g_q + go);
        uint32_t sd = sb + AT_STG(2) + (uint32_t)(row * AT_RSB + c0);
#pragma unroll
        for (int i = 0; i < 4; i++)
            cpasync16(sd + i * 16, qp + c0 + i * 16);
    }
    CP_COMMIT();                                     // g0: Q
    at_load_kv(sb + AT_STG(0), base, 0, tid);
    CP_COMMIT();                                     // g1: KV0
    at_load_kv(sb + AT_STG(1), base, 64, tid);
    CP_COMMIT();                                     // g2: KV1

    uint32_t qh[4][4];
    float    s[8][4], o[8][4];
    float m0 = -1e30f, m1 = -1e30f, l0 = 0.0f, l1 = 0.0f;
#pragma unroll
    for (int i = 0; i < 8; i++)
#pragma unroll
        for (int j = 0; j < 4; j++) o[i][j] = 0.0f;

    const int lrow8 = (lane & 7) + ((lane >> 3) & 1) * 8;
    const int lhi16 = (lane >> 4);

    int sidx = 0;
    for (int t = 0; t < NKT; t++) {
        if (t + 1 < NKT) { CP_WAIT1(); } else { CP_WAIT0(); }
        __syncthreads();

        if (t == 0) {
#pragma unroll
            for (int j = 0; j < 4; j++) {
                uint32_t a = sb + AT_STG(2) +
                    (uint32_t)((wid * 16 + lrow8) * AT_RSB + j * 32 + lhi16 * 16);
                ldsm4(qh[j], a);
            }
            __syncthreads();
        }

        if (t + 2 < NKT) {
            int ps = sidx + 2; if (ps >= 3) ps -= 3;
            at_load_kv(sb + AT_STG(ps), base, (t + 2) * 64, tid);
            CP_COMMIT();
        }

        const uint32_t st  = sb + AT_STG(sidx);
        const uint32_t skh = st + 0 * AT_KTILE;
        const uint32_t svh = st + 2 * AT_KTILE;

        // ---- S = Q · (Kh + Kl) : 4 MMA per (nt, k32-group) ----
#pragma unroll
        for (int nt = 0; nt < 8; nt++) {
#pragma unroll
            for (int j = 0; j < 4; j++) s[nt][j] = 0.0f;
#pragma unroll
            for (int g = 0; g < 2; g++) {
                uint32_t kb[4], klb[4];
                uint32_t a = skh +
                    (uint32_t)((nt * 8 + (lane & 7)) * AT_RSB + g * 64 + (lane >> 3) * 16);
                ldsm4(kb,  a);
                ldsm4(klb, a + AT_KTILE);
                mma_fp16(s[nt], qh[2 * g],     kb);
                mma_fp16(s[nt], qh[2 * g],     klb);
                mma_fp16(s[nt], qh[2 * g + 1], kb + 2);
                mma_fp16(s[nt], qh[2 * g + 1], klb + 2);
            }
        }

        // ---- online softmax (base-2; scale folded into Q) ----
        float tm0 = -1e30f, tm1 = -1e30f;
#pragma unroll
        for (int nt = 0; nt < 8; nt++) {
            tm0 = fmaxf(tm0, fmaxf(s[nt][0], s[nt][1]));
            tm1 = fmaxf(tm1, fmaxf(s[nt][2], s[nt][3]));
        }
        tm0 = fmaxf(tm0, __shfl_xor_sync(0xffffffffu, tm0, 1));
        tm0 = fmaxf(tm0, __shfl_xor_sync(0xffffffffu, tm0, 2));
        tm1 = fmaxf(tm1, __shfl_xor_sync(0xffffffffu, tm1, 1));
        tm1 = fmaxf(tm1, __shfl_xor_sync(0xffffffffu, tm1, 2));

        float mn0 = fmaxf(m0, tm0), mn1 = fmaxf(m1, tm1);
        float cr0 = ex2(m0 - mn0),  cr1 = ex2(m1 - mn1);
        m0 = mn0; m1 = mn1;

        uint32_t ah[4][4];
        float rs0 = 0.0f, rs1 = 0.0f;
#pragma unroll
        for (int nt = 0; nt < 8; nt++) {
            float p0 = ex2(s[nt][0] - mn0);
            float p1 = ex2(s[nt][1] - mn0);
            float p2 = ex2(s[nt][2] - mn1);
            float p3 = ex2(s[nt][3] - mn1);
            rs0 += p0 + p1;
            rs1 += p2 + p3;
            int kg = nt >> 1, hf = (nt & 1) * 2;
            ah[kg][hf + 0] = packh2(p0, p1);
            ah[kg][hf + 1] = packh2(p2, p3);
        }
        rs0 += __shfl_xor_sync(0xffffffffu, rs0, 1);
        rs0 += __shfl_xor_sync(0xffffffffu, rs0, 2);
        rs1 += __shfl_xor_sync(0xffffffffu, rs1, 1);
        rs1 += __shfl_xor_sync(0xffffffffu, rs1, 2);
        l0 = l0 * cr0 + rs0;
        l1 = l1 * cr1 + rs1;
#pragma unroll
        for (int nt = 0; nt < 8; nt++) {
            o[nt][0] *= cr0; o[nt][1] *= cr0;
            o[nt][2] *= cr1; o[nt][3] *= cr1;
        }

        // ---- O += P · (Vh + Vl) : 4 MMA per (dp, kg) ----
#pragma unroll
        for (int dp = 0; dp < 4; dp++) {
#pragma unroll
            for (int kg = 0; kg < 4; kg++) {
                uint32_t vb[4], vlb[4];
                uint32_t a = svh +
                    (uint32_t)((kg * 16 + lrow8) * AT_RSB + dp * 32 + lhi16 * 16);
                ldsm4t(vb,  a);
                ldsm4t(vlb, a + AT_KTILE);
                mma_fp16(o[2 * dp],     ah[kg], vb);
                mma_fp16(o[2 * dp],     ah[kg], vlb);
                mma_fp16(o[2 * dp + 1], ah[kg], vb + 2);
                mma_fp16(o[2 * dp + 1], ah[kg], vlb + 2);
            }
        }

        if (++sidx == 3) sidx = 0;
    }

    // ---- epilogue: normalize, fp16 single store ----
    float inv0 = 1.0f / l0, inv1 = 1.0f / l1;
    int r0 = q0 + wid * 16 + (lane >> 2);
    int cbase = (lane & 3) * 2;
#pragma unroll
    for (int nt = 0; nt < 8; nt++) {
        int col = nt * 8 + cbase;
        size_t o0 = base + (size_t)r0 * HIDDEN + col;
        size_t o1 = base + (size_t)(r0 + 8) * HIDDEN + col;
        *(uint32_t*)&g_ao[o0] = packh2(o[nt][0] * inv0, o[nt][1] * inv0);
        *(uint32_t*)&g_ao[o1] = packh2(o[nt][2] * inv1, o[nt][3] * inv1);
    }
}

// ---------------------------------------------------------------------------
extern "C" void kernel_launch(void* const* d_in, const int* in_sizes, int n_in,
                              void* d_out, int out_size)
{
    const float* x  = (const float*)d_in[0];
    const float* Wq = (const float*)d_in[1];
    const float* bq = (const float*)d_in[2];
    const float* Wk = (const float*)d_in[3];
    const float* bk = (const float*)d_in[4];
    const float* Wv = (const float*)d_in[5];
    const float* bv = (const float*)d_in[6];
    const float* Wo = (const float*)d_in[7];
    const float* bo = (const float*)d_in[8];
    float* out = (float*)d_out;

    static int attr_set = 0;
    if (!attr_set) {
        cudaFuncSetAttribute(gemm_qkv_kernel,
                             cudaFuncAttributeMaxDynamicSharedMemorySize, GSMEM);
        cudaFuncSetAttribute(gemm_o_kernel,
                             cudaFuncAttributeMaxDynamicSharedMemorySize, GSMEM);
        cudaFuncSetAttribute(attn_mma_kernel,
                             cudaFuncAttributeMaxDynamicSharedMemorySize, AT_SMEM);
        attr_set = 1;
    }

    split_x_kernel<<<MTOT * HIDDEN / 1024, 256>>>(x);
    wtrans_kernel<<<dim3(32, 32, 4), dim3(32, 8)>>>(Wq, Wk, Wv, Wo);
    gemm_qkv_kernel<<<dim3(HIDDEN / 128, MTOT / 128, 3), 256, GSMEM>>>(bq, bk, bv);
    attn_mma_kernel<<<dim3(SEQ / 128, HEADS, BATCH), 256, AT_SMEM>>>();
    gemm_o_kernel<<<dim3(HIDDEN / 128, MTOT / 128, 1), 256, GSMEM>>>(bo, out);
}

// round 9
// speedup vs baseline: 5.9087x; 1.7430x over previous
#include <cuda_runtime.h>
#include <cuda_fp16.h>
#include <cstdint>

#define HIDDEN 1024
#define SEQ    2048
#define BATCH  2
#define HEADS  16
#define HD     64
#define MTOT   (BATCH*SEQ)   // 4096

typedef __half fp16;

// Scale folded into Q projection: 1/sqrt(64) * log2(e)
#define SCALE_Q (0.125f * 1.4426950408889634f)

// ---------------- scratch (device globals) -----------------------------------
__device__ fp16 g_x  [MTOT*HIDDEN];       // x, fp16
__device__ fp16 g_q  [MTOT*HIDDEN];       // Q, fp16, pre-scaled
__device__ fp16 g_k  [MTOT*HIDDEN];
__device__ fp16 g_v  [MTOT*HIDDEN];
__device__ fp16 g_ao [MTOT*HIDDEN];       // attn out, fp16
__device__ fp16 g_w  [4*HIDDEN*HIDDEN];   // W^T, [n][k], fp16

// ---------------- helpers ----------------------------------------------------
__device__ __forceinline__ uint32_t smem_u32(const void* p) {
    uint32_t a;
    asm("{ .reg .u64 t; cvta.to.shared.u64 t, %1; cvt.u32.u64 %0, t; }"
        : "=r"(a) : "l"(p));
    return a;
}
__device__ __forceinline__ void cpasync16(uint32_t dst, const void* src) {
    asm volatile("cp.async.cg.shared.global [%0], [%1], 16;"
                 :: "r"(dst), "l"(src));
}
#define CP_COMMIT() asm volatile("cp.async.commit_group;" ::: "memory")
#define CP_WAIT1()  asm volatile("cp.async.wait_group 1;"  ::: "memory")
#define CP_WAIT0()  asm volatile("cp.async.wait_group 0;"  ::: "memory")

__device__ __forceinline__ void mma_fp16(float* c, const uint32_t* a,
                                         const uint32_t* b) {
    asm volatile(
        "mma.sync.aligned.m16n8k16.row.col.f32.f16.f16.f32 "
        "{%0,%1,%2,%3}, {%4,%5,%6,%7}, {%8,%9}, {%0,%1,%2,%3};"
        : "+f"(c[0]), "+f"(c[1]), "+f"(c[2]), "+f"(c[3])
        : "r"(a[0]), "r"(a[1]), "r"(a[2]), "r"(a[3]), "r"(b[0]), "r"(b[1]));
}
__device__ __forceinline__ void ldsm4(uint32_t* r, uint32_t addr) {
    asm volatile("ldmatrix.sync.aligned.m8n8.x4.shared.b16 {%0,%1,%2,%3}, [%4];"
                 : "=r"(r[0]), "=r"(r[1]), "=r"(r[2]), "=r"(r[3]) : "r"(addr));
}
__device__ __forceinline__ void ldsm4t(uint32_t* r, uint32_t addr) {
    asm volatile("ldmatrix.sync.aligned.m8n8.x4.trans.shared.b16 {%0,%1,%2,%3}, [%4];"
                 : "=r"(r[0]), "=r"(r[1]), "=r"(r[2]), "=r"(r[3]) : "r"(addr));
}
__device__ __forceinline__ float ex2(float x) {
    float y;
    asm("ex2.approx.ftz.f32 %0, %1;" : "=f"(y) : "f"(x));
    return y;
}
__device__ __forceinline__ uint32_t packh2(float a, float b) {
    __half2 t = __floats2half2_rn(a, b);   // .x = a (low half)
    return *(uint32_t*)&t;
}

// ---------------- prep: x -> fp16 --------------------------------------------
__global__ __launch_bounds__(256) void split_x_kernel(const float* __restrict__ src) {
    int i = (blockIdx.x * 256 + threadIdx.x) * 4;
    float4 v = *(const float4*)&src[i];
    uint2 o;
    o.x = packh2(v.x, v.y);
    o.y = packh2(v.z, v.w);
    *(uint2*)&g_x[i] = o;
}

// ---------------- transpose weights: W[K][N] -> Wt[N][K] fp16 ----------------
__global__ __launch_bounds__(256) void wtrans_kernel(
    const float* __restrict__ W0, const float* __restrict__ W1,
    const float* __restrict__ W2, const float* __restrict__ W3)
{
    __shared__ float t[32][33];
    const float* W = (blockIdx.z == 0) ? W0 : (blockIdx.z == 1) ? W1
                   : (blockIdx.z == 2) ? W2 : W3;
    fp16* ow = g_w + (size_t)blockIdx.z * HIDDEN * HIDDEN;
    int n0 = blockIdx.x * 32, k0 = blockIdx.y * 32;
    int tx = threadIdx.x, ty = threadIdx.y;
#pragma unroll
    for (int i = 0; i < 4; i++)
        t[ty + 8 * i][tx] = W[(size_t)(k0 + ty + 8 * i) * HIDDEN + n0 + tx];
    __syncthreads();
#pragma unroll
    for (int i = 0; i < 4; i++)
        ow[(size_t)(n0 + ty + 8 * i) * HIDDEN + k0 + tx] =
            __float2half_rn(t[tx][ty + 8 * i]);
}

// ---------------- fp16 GEMM via mma.sync + ldmatrix --------------------------
// C = A @ W^T + bias. CTA 128x128, K-chunk 32, 256 threads.
#define KCH    32
#define NCHK   (HIDDEN / KCH)   // 32
#define ARR_B  (128 * 80)            // 10240 bytes per array
#define STG_B  (2 * ARR_B)           // 20480 bytes
#define GSMEM  (2 * STG_B)           // 40960 bytes

__device__ __forceinline__ void g_load_stage(
    uint32_t sbase, const fp16* __restrict__ A,
    const fp16* __restrict__ B, int ko, int tid)
{
#pragma unroll
    for (int l = 0; l < 2; l++) {
        int fi  = tid + 256 * l;
        int row = fi >> 2;
        int w   = fi & 3;
        uint32_t so = sbase + (uint32_t)(row * 80 + w * 16);
        size_t   go = (size_t)row * HIDDEN + ko + w * 8;
        cpasync16(so + 0 * ARR_B, A + go);
        cpasync16(so + 1 * ARR_B, B + go);
    }
}

// Per warp per chunk: 8 A-ldsm + 4 B-ldsm + 32 HMMA.
__device__ __forceinline__ void g_compute_ldsm(
    uint32_t sb, int m_w, int n_w, int lane, float acc[4][4][4])
{
    const int lrow8 = (lane & 7) + ((lane >> 3) & 1) * 8;
    const int lhi16 = lane >> 4;
    const int bcol  = (lane >> 3) * 16;

    uint32_t B[4][4];
#pragma unroll
    for (int ni = 0; ni < 4; ni++) {
        uint32_t a = sb + 1 * ARR_B +
                     (uint32_t)((n_w + ni * 8 + (lane & 7)) * 80 + bcol);
        ldsm4(B[ni], a);
    }

#pragma unroll
    for (int ks = 0; ks < 2; ks++) {
#pragma unroll
        for (int mi = 0; mi < 4; mi++) {
            uint32_t a = sb +
                (uint32_t)((m_w + mi * 16 + lrow8) * 80 + ks * 32 + lhi16 * 16);
            uint32_t ar[4];
            ldsm4(ar, a);
#pragma unroll
            for (int ni = 0; ni < 4; ni++)
                mma_fp16(acc[mi][ni], ar, B[ni] + 2 * ks);
        }
    }
}

// Epilogue: Cf != 0 -> fp32 out; else fp16 out.
__device__ __forceinline__ void gemm_body_mma(
    const fp16* __restrict__ A0, const fp16* __restrict__ B0,
    const float* __restrict__ bias,
    float* __restrict__ Cf, fp16* __restrict__ Ch,
    float scale, int m0, int n0)
{
    extern __shared__ char sm[];
    const int tid  = threadIdx.x;
    const int wid  = tid >> 5;
    const int lane = tid & 31;
    const int lr = lane >> 2, lc = lane & 3;
    const int m_w = (wid & 1) * 64;
    const int n_w = (wid >> 1) * 32;

    const fp16* A = A0 + (size_t)m0 * HIDDEN;
    const fp16* B = B0 + (size_t)n0 * HIDDEN;

    float acc[4][4][4];
#pragma unroll
    for (int i = 0; i < 4; i++)
#pragma unroll
        for (int j = 0; j < 4; j++)
#pragma unroll
            for (int k = 0; k < 4; k++) acc[i][j][k] = 0.0f;

    const uint32_t sb = smem_u32(sm);
    g_load_stage(sb, A, B, 0, tid);
    CP_COMMIT();

    for (int c = 0; c < NCHK; c++) {
        CP_WAIT0();
        __syncthreads();
        if (c + 1 < NCHK) {
            g_load_stage(sb + ((c + 1) & 1) * STG_B, A, B, (c + 1) * KCH, tid);
            CP_COMMIT();
        }
        g_compute_ldsm(sb + (c & 1) * STG_B, m_w, n_w, lane, acc);
    }

#pragma unroll
    for (int mi = 0; mi < 4; mi++) {
#pragma unroll
        for (int ni = 0; ni < 4; ni++) {
            int row = m0 + m_w + mi * 16 + lr;
            int col = n0 + n_w + ni * 8 + lc * 2;
            float b0 = bias[col], b1 = bias[col + 1];
            float v00 = (acc[mi][ni][0] + b0) * scale;
            float v01 = (acc[mi][ni][1] + b1) * scale;
            float v10 = (acc[mi][ni][2] + b0) * scale;
            float v11 = (acc[mi][ni][3] + b1) * scale;
            if (Cf) {
                *(float2*)&Cf[(size_t)row * HIDDEN + col]       = make_float2(v00, v01);
                *(float2*)&Cf[(size_t)(row + 8) * HIDDEN + col] = make_float2(v10, v11);
            } else {
                *(uint32_t*)&Ch[(size_t)row * HIDDEN + col]       = packh2(v00, v01);
                *(uint32_t*)&Ch[(size_t)(row + 8) * HIDDEN + col] = packh2(v10, v11);
            }
        }
    }
}

__global__ __launch_bounds__(256, 2) void gemm_qkv_kernel(
    const float* __restrict__ bq, const float* __restrict__ bk,
    const float* __restrict__ bv)
{
    const fp16* B; const float* bias; fp16* C; float scale;
    if (blockIdx.z == 0)      { B = g_w;                       bias = bq; C = g_q; scale = SCALE_Q; }
    else if (blockIdx.z == 1) { B = g_w + 1 * HIDDEN * HIDDEN; bias = bk; C = g_k; scale = 1.0f; }
    else                      { B = g_w + 2 * HIDDEN * HIDDEN; bias = bv; C = g_v; scale = 1.0f; }
    gemm_body_mma(g_x, B, bias, nullptr, C, scale,
                  blockIdx.y * 128, blockIdx.x * 128);
}

__global__ __launch_bounds__(256, 2) void gemm_o_kernel(
    const float* __restrict__ bo, float* __restrict__ out)
{
    gemm_body_mma(g_ao, g_w + 3 * HIDDEN * HIDDEN, bo, out, nullptr, 1.0f,
                  blockIdx.y * 128, blockIdx.x * 128);
}

// ---------------- flash attention, plain fp16 --------------------------------
// CTA: 256 threads (8 warps), q-tile 128, key tiles of 64, 3-stage KV pipeline.
#define AT_RSB   144
#define AT_KTILE (64 * AT_RSB)                  // 9216
#define AT_STGB  (2 * AT_KTILE)                 // 18432 per stage (K + V)
#define AT_STG(s) ((s) * AT_STGB)
#define AT_QOFF  (3 * AT_STGB)                  // Q staged after 3 stages
#define AT_SMEM  (3 * AT_STGB + 18432)          // 73728 -> regs bind at 2 CTA/SM
#define NKT      (SEQ / 64)                     // 32

__device__ __forceinline__ void at_load_kv(uint32_t sdst, size_t gbase,
                                           int kt, int tid)
{
    int row = tid >> 2;               // 0..63
    int c0  = (tid & 3) * 32;         // 0,32,64,96 bytes
    size_t go = gbase + (size_t)(kt + row) * HIDDEN;
    const char* kp = (const char*)(g_k + go);
    const char* vp = (const char*)(g_v + go);
    uint32_t sd = sdst + (uint32_t)(row * AT_RSB + c0);
#pragma unroll
    for (int i = 0; i < 2; i++) {
        cpasync16(sd + 0 * AT_KTILE + i * 16, kp + c0 + i * 16);
        cpasync16(sd + 1 * AT_KTILE + i * 16, vp + c0 + i * 16);
    }
}

__global__ __launch_bounds__(256, 2) void attn_mma_kernel()
{
    extern __shared__ char sma[];
    const int tid  = threadIdx.x;
    const int wid  = tid >> 5;
    const int lane = tid & 31;
    const int q0 = blockIdx.x * 128;
    const int h  = blockIdx.y;
    const int b  = blockIdx.z;
    const size_t base = (size_t)b * SEQ * HIDDEN + (size_t)h * HD;
    const uint32_t sb = smem_u32(sma);

    // Q (fp16) into its own staging area (no recycling hazard).
    {
        int row = tid >> 1;
        int c0  = (tid & 1) * 64;
        size_t go = base + (size_t)(q0 + row) * HIDDEN;
        const char* qp = (const char*)(g_q + go);
        uint32_t sd = sb + AT_QOFF + (uint32_t)(row * AT_RSB + c0);
#pragma unroll
        for (int i = 0; i < 4; i++)
            cpasync16(sd + i * 16, qp + c0 + i * 16);
    }
    CP_COMMIT();                                     // g0: Q
    at_load_kv(sb + AT_STG(0), base, 0, tid);
    CP_COMMIT();                                     // g1: KV0
    at_load_kv(sb + AT_STG(1), base, 64, tid);
    CP_COMMIT();                                     // g2: KV1

    uint32_t qh[4][4];
    float    s[8][4], o[8][4];
    float m0 = -1e30f, m1 = -1e30f, l0 = 0.0f, l1 = 0.0f;
#pragma unroll
    for (int i = 0; i < 8; i++)
#pragma unroll
        for (int j = 0; j < 4; j++) o[i][j] = 0.0f;

    const int lrow8 = (lane & 7) + ((lane >> 3) & 1) * 8;
    const int lhi16 = (lane >> 4);

    int sidx = 0;
    for (int t = 0; t < NKT; t++) {
        if (t + 1 < NKT) { CP_WAIT1(); } else { CP_WAIT0(); }
        __syncthreads();

        if (t == 0) {
#pragma unroll
            for (int j = 0; j < 4; j++) {
                uint32_t a = sb + AT_QOFF +
                    (uint32_t)((wid * 16 + lrow8) * AT_RSB + j * 32 + lhi16 * 16);
                ldsm4(qh[j], a);
            }
        }

        if (t + 2 < NKT) {
            int ps = sidx + 2; if (ps >= 3) ps -= 3;
            at_load_kv(sb + AT_STG(ps), base, (t + 2) * 64, tid);
            CP_COMMIT();
        }

        const uint32_t skh = sb + AT_STG(sidx);
        const uint32_t svh = skh + AT_KTILE;

        // ---- S = Q · K^T : 2 MMA per (nt, k32-group) ----
#pragma unroll
        for (int nt = 0; nt < 8; nt++) {
#pragma unroll
            for (int j = 0; j < 4; j++) s[nt][j] = 0.0f;
#pragma unroll
            for (int g = 0; g < 2; g++) {
                uint32_t kb[4];
                uint32_t a = skh +
                    (uint32_t)((nt * 8 + (lane & 7)) * AT_RSB + g * 64 + (lane >> 3) * 16);
                ldsm4(kb, a);
                mma_fp16(s[nt], qh[2 * g],     kb);
                mma_fp16(s[nt], qh[2 * g + 1], kb + 2);
            }
        }

        // ---- online softmax (base-2; scale folded into Q) ----
        float tm0 = -1e30f, tm1 = -1e30f;
#pragma unroll
        for (int nt = 0; nt < 8; nt++) {
            tm0 = fmaxf(tm0, fmaxf(s[nt][0], s[nt][1]));
            tm1 = fmaxf(tm1, fmaxf(s[nt][2], s[nt][3]));
        }
        tm0 = fmaxf(tm0, __shfl_xor_sync(0xffffffffu, tm0, 1));
        tm0 = fmaxf(tm0, __shfl_xor_sync(0xffffffffu, tm0, 2));
        tm1 = fmaxf(tm1, __shfl_xor_sync(0xffffffffu, tm1, 1));
        tm1 = fmaxf(tm1, __shfl_xor_sync(0xffffffffu, tm1, 2));

        float mn0 = fmaxf(m0, tm0), mn1 = fmaxf(m1, tm1);
        float cr0 = ex2(m0 - mn0),  cr1 = ex2(m1 - mn1);
        m0 = mn0; m1 = mn1;

        uint32_t ah[4][4];
        float rs0 = 0.0f, rs1 = 0.0f;
#pragma unroll
        for (int nt = 0; nt < 8; nt++) {
            float p0 = ex2(s[nt][0] - mn0);
            float p1 = ex2(s[nt][1] - mn0);
            float p2 = ex2(s[nt][2] - mn1);
            float p3 = ex2(s[nt][3] - mn1);
            rs0 += p0 + p1;
            rs1 += p2 + p3;
            int kg = nt >> 1, hf = (nt & 1) * 2;
            ah[kg][hf + 0] = packh2(p0, p1);
            ah[kg][hf + 1] = packh2(p2, p3);
        }
        rs0 += __shfl_xor_sync(0xffffffffu, rs0, 1);
        rs0 += __shfl_xor_sync(0xffffffffu, rs0, 2);
        rs1 += __shfl_xor_sync(0xffffffffu, rs1, 1);
        rs1 += __shfl_xor_sync(0xffffffffu, rs1, 2);
        l0 = l0 * cr0 + rs0;
        l1 = l1 * cr1 + rs1;
#pragma unroll
        for (int nt = 0; nt < 8; nt++) {
            o[nt][0] *= cr0; o[nt][1] *= cr0;
            o[nt][2] *= cr1; o[nt][3] *= cr1;
        }

        // ---- O += P · V : 2 MMA per (dp, kg) ----
#pragma unroll
        for (int dp = 0; dp < 4; dp++) {
#pragma unroll
            for (int kg = 0; kg < 4; kg++) {
                uint32_t vb[4];
                uint32_t a = svh +
                    (uint32_t)((kg * 16 + lrow8) * AT_RSB + dp * 32 + lhi16 * 16);
                ldsm4t(vb, a);
                mma_fp16(o[2 * dp],     ah[kg], vb);
                mma_fp16(o[2 * dp + 1], ah[kg], vb + 2);
            }
        }

        if (++sidx == 3) sidx = 0;
    }

    // ---- epilogue: normalize, fp16 store ----
    float inv0 = 1.0f / l0, inv1 = 1.0f / l1;
    int r0 = q0 + wid * 16 + (lane >> 2);
    int cbase = (lane & 3) * 2;
#pragma unroll
    for (int nt = 0; nt < 8; nt++) {
        int col = nt * 8 + cbase;
        size_t o0 = base + (size_t)r0 * HIDDEN + col;
        size_t o1 = base + (size_t)(r0 + 8) * HIDDEN + col;
        *(uint32_t*)&g_ao[o0] = packh2(o[nt][0] * inv0, o[nt][1] * inv0);
        *(uint32_t*)&g_ao[o1] = packh2(o[nt][2] * inv1, o[nt][3] * inv1);
    }
}

// ---------------------------------------------------------------------------
extern "C" void kernel_launch(void* const* d_in, const int* in_sizes, int n_in,
                              void* d_out, int out_size)
{
    const float* x  = (const float*)d_in[0];
    const float* Wq = (const float*)d_in[1];
    const float* bq = (const float*)d_in[2];
    const float* Wk = (const float*)d_in[3];
    const float* bk = (const float*)d_in[4];
    const float* Wv = (const float*)d_in[5];
    const float* bv = (const float*)d_in[6];
    const float* Wo = (const float*)d_in[7];
    const float* bo = (const float*)d_in[8];
    float* out = (float*)d_out;

    static int attr_set = 0;
    if (!attr_set) {
        cudaFuncSetAttribute(gemm_qkv_kernel,
                             cudaFuncAttributeMaxDynamicSharedMemorySize, GSMEM);
        cudaFuncSetAttribute(gemm_o_kernel,
                             cudaFuncAttributeMaxDynamicSharedMemorySize, GSMEM);
        cudaFuncSetAttribute(attn_mma_kernel,
                             cudaFuncAttributeMaxDynamicSharedMemorySize, AT_SMEM);
        attr_set = 1;
    }

    split_x_kernel<<<MTOT * HIDDEN / 1024, 256>>>(x);
    wtrans_kernel<<<dim3(32, 32, 4), dim3(32, 8)>>>(Wq, Wk, Wv, Wo);
    gemm_qkv_kernel<<<dim3(HIDDEN / 128, MTOT / 128, 3), 256, GSMEM>>>(bq, bk, bv);
    attn_mma_kernel<<<dim3(SEQ / 128, HEADS, BATCH), 256, AT_SMEM>>>();
    gemm_o_kernel<<<dim3(HIDDEN / 128, MTOT / 128, 1), 256, GSMEM>>>(bo, out);
}